// round 6
// baseline (speedup 1.0000x reference)
#include <cuda_runtime.h>
#include <cuda_bf16.h>
#include <cstdint>

#define NN   100000
#define NE   1600000
#define NGR  128
#define D_   128
#define DO_  64
#define BN_EPS 1e-5f
#define SCAN_ELEMS 2048
#define NBLK ((NN + SCAN_ELEMS - 1) / SCAN_ELEMS)   // 49

typedef unsigned long long ull;

// ---------------- scratch ----------------
__device__ __align__(16) float g_agg[(size_t)NN * D_];
__device__ __align__(16) float g_hid[(size_t)NN * D_];
__device__ __align__(16) float g_h1 [(size_t)NN * D_];
__device__ __align__(16) float g_h2 [(size_t)NN * D_];
__device__ __align__(16) float g_bnstats[2 * D_];
__device__ __align__(16) float g_scale[D_];
__device__ __align__(16) float g_shift[D_];
__device__ __align__(16) float g_pool[NGR * DO_];
__device__ __align__(16) int   g_cnt[NGR];
// CSR scratch
__device__ __align__(16) int g_deg[NN];
__device__ __align__(16) int g_off[NN + 1];
__device__ __align__(16) int g_cur[NN];
__device__ __align__(16) int g_csr[NE];
__device__ int g_bsum[64];
__device__ int g_bscan[64];
// pre-split, pre-swizzled W images: [k][n] row-major bf16, 16B-chunk XOR swizzle
__device__ __align__(16) unsigned char g_whi[6 * 32768];
__device__ __align__(16) unsigned char g_wlo[6 * 32768];

// ---------------- asm helpers ----------------
__device__ __forceinline__ uint32_t smem_u32(const void* p) {
    uint32_t a;
    asm("{ .reg .u64 t; cvta.to.shared.u64 t, %1; cvt.u32.u64 %0, t; }" : "=r"(a) : "l"(p));
    return a;
}
__device__ __forceinline__ void ldsm_x4(uint32_t& r0, uint32_t& r1, uint32_t& r2, uint32_t& r3,
                                        uint32_t addr) {
    asm volatile("ldmatrix.sync.aligned.m8n8.x4.shared.b16 {%0,%1,%2,%3}, [%4];"
                 : "=r"(r0), "=r"(r1), "=r"(r2), "=r"(r3) : "r"(addr));
}
__device__ __forceinline__ void ldsm_x4t(uint32_t& r0, uint32_t& r1, uint32_t& r2, uint32_t& r3,
                                         uint32_t addr) {
    asm volatile("ldmatrix.sync.aligned.m8n8.x4.trans.shared.b16 {%0,%1,%2,%3}, [%4];"
                 : "=r"(r0), "=r"(r1), "=r"(r2), "=r"(r3) : "r"(addr));
}
__device__ __forceinline__ void mma16816(float* c, uint32_t a0, uint32_t a1, uint32_t a2,
                                         uint32_t a3, uint32_t b0, uint32_t b1) {
    asm volatile("mma.sync.aligned.m16n8k16.row.col.f32.bf16.bf16.f32 "
                 "{%0,%1,%2,%3}, {%4,%5,%6,%7}, {%8,%9}, {%0,%1,%2,%3};"
                 : "+f"(c[0]), "+f"(c[1]), "+f"(c[2]), "+f"(c[3])
                 : "r"(a0), "r"(a1), "r"(a2), "r"(a3), "r"(b0), "r"(b1));
}

// ---------------- utility ----------------
__global__ void zero_kernel(float* __restrict__ p, int n4) {
    int i = blockIdx.x * blockDim.x + threadIdx.x;
    if (i < n4) ((float4*)p)[i] = make_float4(0.f, 0.f, 0.f, 0.f);
}

// ---------------- CSR build ----------------
__global__ void hist_kernel(const int* __restrict__ dst) {
    int i = blockIdx.x * blockDim.x + threadIdx.x;
    if (i < NE) atomicAdd(&g_deg[__ldg(dst + i)], 1);
}
__global__ void scan_pass1() {
    __shared__ int ssum[8];
    int b = blockIdx.x, tid = threadIdx.x;
    int base = b * SCAN_ELEMS + tid * 8;
    int s = 0;
    #pragma unroll
    for (int j = 0; j < 8; j++) { int idx = base + j; s += (idx < NN) ? g_deg[idx] : 0; }
    #pragma unroll
    for (int o = 16; o; o >>= 1) s += __shfl_down_sync(0xffffffffu, s, o);
    if ((tid & 31) == 0) ssum[tid >> 5] = s;
    __syncthreads();
    if (tid == 0) {
        int t = 0;
        #pragma unroll
        for (int i = 0; i < 8; i++) t += ssum[i];
        g_bsum[b] = t;
    }
}
__global__ void scan_pass2() {
    int tid = threadIdx.x;
    int v = (tid < NBLK) ? g_bsum[tid] : 0;
    int incl = v, lane = tid & 31;
    #pragma unroll
    for (int o = 1; o < 32; o <<= 1) {
        int y = __shfl_up_sync(0xffffffffu, incl, o);
        if (lane >= o) incl += y;
    }
    __shared__ int w0;
    if (tid == 31) w0 = incl;
    __syncthreads();
    if (tid >= 32) incl += w0;
    if (tid < 64) g_bscan[tid] = incl - v;
    if (tid == 0) g_off[NN] = NE;
}
__global__ void scan_pass3() {
    int b = blockIdx.x, tid = threadIdx.x;
    int base = b * SCAN_ELEMS + tid * 8;
    int vals[8], t = 0;
    #pragma unroll
    for (int j = 0; j < 8; j++) { vals[j] = (base + j < NN) ? g_deg[base + j] : 0; t += vals[j]; }
    int lane = tid & 31, wid = tid >> 5, incl = t;
    #pragma unroll
    for (int o = 1; o < 32; o <<= 1) {
        int y = __shfl_up_sync(0xffffffffu, incl, o);
        if (lane >= o) incl += y;
    }
    __shared__ int wsum[8], woff[8];
    if (lane == 31) wsum[wid] = incl;
    __syncthreads();
    if (tid == 0) { int a = 0; for (int i = 0; i < 8; i++) { woff[i] = a; a += wsum[i]; } }
    __syncthreads();
    int run = g_bscan[b] + woff[wid] + (incl - t);
    #pragma unroll
    for (int j = 0; j < 8; j++) {
        int idx = base + j;
        if (idx < NN) { g_off[idx] = run; g_cur[idx] = run; run += vals[j]; }
    }
}
__global__ void fill_kernel(const int* __restrict__ src, const int* __restrict__ dst) {
    int i = blockIdx.x * blockDim.x + threadIdx.x;
    if (i < NE) {
        int d = __ldg(dst + i);
        int p = atomicAdd(&g_cur[d], 1);
        g_csr[p] = __ldg(src + i);
    }
}

// ---------------- W split + swizzle preconvert ----------------
__global__ void wconv_kernel(const float* w0, const float* w1, const float* w2,
                             const float* w3, const float* w4, const float* w5)
{
    int i = blockIdx.x * blockDim.x + threadIdx.x;
    if (i >= 5 * 16384 + 8192) return;
    int seg = i >> 14;
    int t = i & 16383;
    int nout = (seg == 5) ? 64 : 128;
    const float* W = (seg == 0) ? w0 : (seg == 1) ? w1 : (seg == 2) ? w2
                   : (seg == 3) ? w3 : (seg == 4) ? w4 : w5;
    int k = t / nout, n = t % nout;
    float w = __ldg(W + k * nout + n);
    __nv_bfloat16 hi = __float2bfloat16(w);
    __nv_bfloat16 lo = __float2bfloat16(w - __bfloat162float(hi));
    int pos = k * nout + ((((n >> 3) ^ (k & 7)) << 3) | (n & 7));
    ((__nv_bfloat16*)(g_whi + seg * 32768))[pos] = hi;
    ((__nv_bfloat16*)(g_wlo + seg * 32768))[pos] = lo;
}

// ---------------- gather ----------------
__device__ __forceinline__ float4 bn_ap(float4 v, float4 sc, float4 sh, bool bn) {
    if (bn) {
        v.x = fmaxf(fmaf(v.x, sc.x, sh.x), 0.f);
        v.y = fmaxf(fmaf(v.y, sc.y, sh.y), 0.f);
        v.z = fmaxf(fmaf(v.z, sc.z, sh.z), 0.f);
        v.w = fmaxf(fmaf(v.w, sc.w, sh.w), 0.f);
    }
    return v;
}
__device__ __forceinline__ void f4acc(float4& a, float4 b) {
    a.x += b.x; a.y += b.y; a.z += b.z; a.w += b.w;
}

template<bool BN>
__global__ void gather_kernel(const float* __restrict__ h, float* __restrict__ out)
{
    int n = blockIdx.x * 8 + (threadIdx.x >> 5);
    if (n >= NN) return;
    int lane = threadIdx.x & 31;
    const float4* __restrict__ h4 = (const float4*)h;

    float4 sc = make_float4(0,0,0,0), sh = make_float4(0,0,0,0);
    if (BN) {
        sc = *(const float4*)(g_scale + lane * 4);
        sh = *(const float4*)(g_shift + lane * 4);
    }
    float4 a0 = bn_ap(__ldg(&h4[(size_t)n * 32 + lane]), sc, sh, BN);
    float4 a1 = make_float4(0,0,0,0), a2 = make_float4(0,0,0,0), a3 = make_float4(0,0,0,0);

    int j = g_off[n], e1 = g_off[n + 1];
    for (; j + 8 <= e1; j += 8) {
        int ix[8];
        #pragma unroll
        for (int u = 0; u < 8; u++) ix[u] = __ldg(&g_csr[j + u]);
        float4 w[8];
        #pragma unroll
        for (int u = 0; u < 8; u++) w[u] = __ldg(&h4[(size_t)ix[u] * 32 + lane]);
        f4acc(a0, bn_ap(w[0], sc, sh, BN));
        f4acc(a1, bn_ap(w[1], sc, sh, BN));
        f4acc(a2, bn_ap(w[2], sc, sh, BN));
        f4acc(a3, bn_ap(w[3], sc, sh, BN));
        f4acc(a0, bn_ap(w[4], sc, sh, BN));
        f4acc(a1, bn_ap(w[5], sc, sh, BN));
        f4acc(a2, bn_ap(w[6], sc, sh, BN));
        f4acc(a3, bn_ap(w[7], sc, sh, BN));
    }
    for (; j + 4 <= e1; j += 4) {
        int i0 = __ldg(&g_csr[j]);
        int i1 = __ldg(&g_csr[j + 1]);
        int i2 = __ldg(&g_csr[j + 2]);
        int i3 = __ldg(&g_csr[j + 3]);
        float4 w0 = __ldg(&h4[(size_t)i0 * 32 + lane]);
        float4 w1 = __ldg(&h4[(size_t)i1 * 32 + lane]);
        float4 w2 = __ldg(&h4[(size_t)i2 * 32 + lane]);
        float4 w3 = __ldg(&h4[(size_t)i3 * 32 + lane]);
        f4acc(a0, bn_ap(w0, sc, sh, BN));
        f4acc(a1, bn_ap(w1, sc, sh, BN));
        f4acc(a2, bn_ap(w2, sc, sh, BN));
        f4acc(a3, bn_ap(w3, sc, sh, BN));
    }
    for (; j < e1; j++) {
        int s = __ldg(&g_csr[j]);
        f4acc(a0, bn_ap(__ldg(&h4[(size_t)s * 32 + lane]), sc, sh, BN));
    }
    f4acc(a0, a1); f4acc(a2, a3); f4acc(a0, a2);
    ((float4*)out)[(size_t)n * 32 + lane] = a0;
}

// ---------------- tensor-core GEMM (mma.sync, split-bf16 3-term) ----------------
// out[N,NOUT] = A[N,128] @ W[128,NOUT] + bias ; 256 thr, 128-row tile,
// warp w handles rows [16w, 16w+16), all NOUT cols. Full K in smem.
// STATS: fused BN column sum/sumsq accumulation (R1/R2-proven pattern).
template<int NOUT, bool RELU, bool STATS>
__global__ __launch_bounds__(256, 1)
void gemm_mma(const float* __restrict__ A,
              const unsigned char* __restrict__ wh, const unsigned char* __restrict__ wl,
              const float* __restrict__ bias, float* __restrict__ out)
{
    constexpr int NT  = NOUT / 8;       // n8 tiles: 16 or 8
    constexpr int BR  = NOUT * 2;       // B row bytes
    constexpr int AHI = 0;
    constexpr int ALO = 32768;
    constexpr int BHI = 65536;
    constexpr int BLO = 65536 + 128 * BR;
    constexpr int STAT = 65536 + 256 * BR;

    extern __shared__ __align__(16) char smem[];
    const uint32_t sb = smem_u32(smem);
    float* s_sum = (float*)(smem + STAT);
    float* s_sq  = s_sum + NOUT;
    const int tid  = threadIdx.x;
    const int wid  = tid >> 5;
    const int lane = tid & 31;
    const int row0 = blockIdx.x * 128;

    // B tiles: straight copy of pre-swizzled images
    {
        const float4* s1 = (const float4*)wh;
        const float4* s2 = (const float4*)wl;
        float4* d1 = (float4*)(smem + BHI);
        float4* d2 = (float4*)(smem + BLO);
        #pragma unroll
        for (int i = tid; i < NOUT * 16; i += 256) { d1[i] = s1[i]; d2[i] = s2[i]; }
    }
    if (STATS && tid < 2 * NOUT) s_sum[tid] = 0.f;
    // A tile: fp32 -> bf16 hi/lo, swizzled 16B chunks (chunk c at c ^ (r&7))
    for (int i = tid; i < 2048; i += 256) {
        int r = i >> 4, c = i & 15;
        int gr = row0 + r;
        float4 v0 = make_float4(0,0,0,0), v1 = make_float4(0,0,0,0);
        if (gr < NN) {
            const float4* ap = (const float4*)(A + (size_t)gr * 128 + c * 8);
            v0 = __ldg(ap); v1 = __ldg(ap + 1);
        }
        float vv[8] = {v0.x, v0.y, v0.z, v0.w, v1.x, v1.y, v1.z, v1.w};
        uint4 hq, lq;
        uint32_t* hp = (uint32_t*)&hq;
        uint32_t* lp = (uint32_t*)&lq;
        #pragma unroll
        for (int p = 0; p < 4; p++) {
            __nv_bfloat162 h2, l2;
            h2.x = __float2bfloat16(vv[2*p]);
            h2.y = __float2bfloat16(vv[2*p+1]);
            l2.x = __float2bfloat16(vv[2*p]   - __bfloat162float(h2.x));
            l2.y = __float2bfloat16(vv[2*p+1] - __bfloat162float(h2.y));
            hp[p] = *(uint32_t*)&h2;
            lp[p] = *(uint32_t*)&l2;
        }
        uint32_t off = (uint32_t)(r * 256 + ((c ^ (r & 7)) << 4));
        *(uint4*)(smem + AHI + off) = hq;
        *(uint4*)(smem + ALO + off) = lq;
    }
    __syncthreads();

    // mainloop
    const int la = lane & 15;
    const int lb = lane >> 4;
    const int l7 = lane & 7;
    const uint32_t aRow = (uint32_t)((wid * 16 + la) * 256);
    const uint32_t bRow = (uint32_t)(la * BR);

    float acc[NT][4];
    #pragma unroll
    for (int t = 0; t < NT; t++)
        #pragma unroll
        for (int e = 0; e < 4; e++) acc[t][e] = 0.f;

    #pragma unroll 2
    for (int k0 = 0; k0 < 128; k0 += 16) {
        uint32_t kc = (uint32_t)((k0 >> 3) + lb);
        uint32_t aoff = aRow + (((kc ^ (uint32_t)l7)) << 4);
        uint32_t ah0, ah1, ah2, ah3, al0, al1, al2, al3;
        ldsm_x4(ah0, ah1, ah2, ah3, sb + AHI + aoff);
        ldsm_x4(al0, al1, al2, al3, sb + ALO + aoff);
        uint32_t bbase = (uint32_t)(k0 * BR) + bRow;
        #pragma unroll
        for (int nt = 0; nt < NT; nt += 2) {
            uint32_t boff = bbase + ((((uint32_t)(nt + lb)) ^ (uint32_t)l7) << 4);
            uint32_t bh0, bh1, bh2, bh3, bl0, bl1, bl2, bl3;
            ldsm_x4t(bh0, bh1, bh2, bh3, sb + BHI + boff);
            ldsm_x4t(bl0, bl1, bl2, bl3, sb + BLO + boff);
            mma16816(acc[nt],     ah0, ah1, ah2, ah3, bh0, bh1);
            mma16816(acc[nt + 1], ah0, ah1, ah2, ah3, bh2, bh3);
            mma16816(acc[nt],     ah0, ah1, ah2, ah3, bl0, bl1);
            mma16816(acc[nt + 1], ah0, ah1, ah2, ah3, bl2, bl3);
            mma16816(acc[nt],     al0, al1, al2, al3, bh0, bh1);
            mma16816(acc[nt + 1], al0, al1, al2, al3, bh2, bh3);
        }
    }

    // epilogue: lane l -> rows (l/4, l/4+8), cols 2*(l%4)+... per n8 tile
    int r1 = row0 + wid * 16 + (lane >> 2);
    int r2 = r1 + 8;
    #pragma unroll
    for (int nt = 0; nt < NT; nt++) {
        int col = nt * 8 + (lane & 3) * 2;
        float2 bb = __ldg((const float2*)(bias + col));
        float v0 = acc[nt][0] + bb.x;
        float v1 = acc[nt][1] + bb.y;
        float v2 = acc[nt][2] + bb.x;
        float v3 = acc[nt][3] + bb.y;
        if (RELU) {
            v0 = fmaxf(v0, 0.f); v1 = fmaxf(v1, 0.f);
            v2 = fmaxf(v2, 0.f); v3 = fmaxf(v3, 0.f);
        }
        if (STATS) {
            float cs0 = 0.f, cs1 = 0.f, cq0 = 0.f, cq1 = 0.f;
            if (r1 < NN) {
                *(float2*)(out + (size_t)r1 * NOUT + col) = make_float2(v0, v1);
                cs0 += v0; cs1 += v1; cq0 += v0 * v0; cq1 += v1 * v1;
            }
            if (r2 < NN) {
                *(float2*)(out + (size_t)r2 * NOUT + col) = make_float2(v2, v3);
                cs0 += v2; cs1 += v3; cq0 += v2 * v2; cq1 += v3 * v3;
            }
            atomicAdd(&s_sum[col],     cs0);
            atomicAdd(&s_sum[col + 1], cs1);
            atomicAdd(&s_sq[col],      cq0);
            atomicAdd(&s_sq[col + 1],  cq1);
        } else {
            if (r1 < NN) *(float2*)(out + (size_t)r1 * NOUT + col) = make_float2(v0, v1);
            if (r2 < NN) *(float2*)(out + (size_t)r2 * NOUT + col) = make_float2(v2, v3);
        }
    }
    if (STATS) {
        __syncthreads();
        if (tid < NOUT) {
            atomicAdd(&g_bnstats[tid], s_sum[tid]);
            atomicAdd(&g_bnstats[NOUT + tid], s_sq[tid]);
        }
    }
}

// ---------------- BN finalize ----------------
__global__ void bn_finalize_kernel(const float* __restrict__ gamma,
                                   const float* __restrict__ beta, int nout)
{
    int c = threadIdx.x;
    if (c < nout) {
        const float invN = 1.0f / (float)NN;
        float mu  = g_bnstats[c] * invN;
        float var = g_bnstats[nout + c] * invN - mu * mu;
        float s   = gamma[c] * rsqrtf(var + BN_EPS);
        g_scale[c] = s;
        g_shift[c] = beta[c] - mu * s;
    }
}

// ---------------- pooling (BN+ReLU fused) ----------------
__global__ void pool_sum_kernel(const float* __restrict__ pre, const int* __restrict__ batch)
{
    int t = blockIdx.x * blockDim.x + threadIdx.x;
    if (t >= NN * 16) return;
    int n = t >> 4, q = t & 15;
    int c = q << 2;
    int b = __ldg(batch + n);
    float4 v  = *(const float4*)(pre + (size_t)n * DO_ + c);
    float4 sc = *(const float4*)(g_scale + c);
    float4 sh = *(const float4*)(g_shift + c);
    v.x = fmaxf(fmaf(v.x, sc.x, sh.x), 0.f);
    v.y = fmaxf(fmaf(v.y, sc.y, sh.y), 0.f);
    v.z = fmaxf(fmaf(v.z, sc.z, sh.z), 0.f);
    v.w = fmaxf(fmaf(v.w, sc.w, sh.w), 0.f);
    float* p = g_pool + b * DO_ + c;
    asm volatile("red.global.add.v4.f32 [%0], {%1, %2, %3, %4};"
                 :: "l"(p), "f"(v.x), "f"(v.y), "f"(v.z), "f"(v.w) : "memory");
}

__global__ void pool_cnt_kernel(const int* __restrict__ batch)
{
    __shared__ int sc[NGR];
    for (int i = threadIdx.x; i < NGR; i += blockDim.x) sc[i] = 0;
    __syncthreads();
    for (int i = blockIdx.x * blockDim.x + threadIdx.x; i < NN; i += gridDim.x * blockDim.x)
        atomicAdd(&sc[__ldg(batch + i)], 1);
    __syncthreads();
    for (int i = threadIdx.x; i < NGR; i += blockDim.x)
        if (sc[i]) atomicAdd(&g_cnt[i], sc[i]);
}

__global__ void pool_fin_kernel(float* __restrict__ out)
{
    int i = blockIdx.x * blockDim.x + threadIdx.x;
    if (i < NGR * DO_) {
        int g = i >> 6;
        float c = (float)(g_cnt[g] > 0 ? g_cnt[g] : 1);
        out[i] = g_pool[i] / c;
    }
}

// ---------------- launcher ----------------
extern "C" void kernel_launch(void* const* d_in, const int* in_sizes, int n_in,
                              void* d_out, int out_size)
{
    const float* x     = (const float*)d_in[0];
    const int*   ei    = (const int*)d_in[1];
    const int*   batch = (const int*)d_in[2];
    const float *wA[3], *bA[3], *wB[3], *bB[3], *gam[3], *bet[3];
    for (int l = 0; l < 3; l++) {
        wA[l]  = (const float*)d_in[3 + 6*l + 0];
        bA[l]  = (const float*)d_in[3 + 6*l + 1];
        wB[l]  = (const float*)d_in[3 + 6*l + 2];
        bB[l]  = (const float*)d_in[3 + 6*l + 3];
        gam[l] = (const float*)d_in[3 + 6*l + 4];
        bet[l] = (const float*)d_in[3 + 6*l + 5];
    }
    const int* src = ei;
    const int* dst = ei + NE;

    float *agg, *hid, *h1, *h2, *bnst, *pool;
    int *cnt, *deg;
    unsigned char *whi, *wlo;
    cudaGetSymbolAddress((void**)&agg,  g_agg);
    cudaGetSymbolAddress((void**)&hid,  g_hid);
    cudaGetSymbolAddress((void**)&h1,   g_h1);
    cudaGetSymbolAddress((void**)&h2,   g_h2);
    cudaGetSymbolAddress((void**)&bnst, g_bnstats);
    cudaGetSymbolAddress((void**)&pool, g_pool);
    cudaGetSymbolAddress((void**)&cnt,  g_cnt);
    cudaGetSymbolAddress((void**)&deg,  g_deg);
    cudaGetSymbolAddress((void**)&whi,  g_whi);
    cudaGetSymbolAddress((void**)&wlo,  g_wlo);

    constexpr int SM128  = 65536 + 2 * 128 * 256;            // 131072 (no stats)
    constexpr int SM128S = 65536 + 2 * 128 * 256 + 1024;     // 132096 (stats)
    constexpr int SM64S  = 65536 + 2 * 64  * 256 + 512;      //  98816 (stats)
    cudaFuncSetAttribute(gemm_mma<128, true,  false>, cudaFuncAttributeMaxDynamicSharedMemorySize, SM128);
    cudaFuncSetAttribute(gemm_mma<128, false, true >, cudaFuncAttributeMaxDynamicSharedMemorySize, SM128S);
    cudaFuncSetAttribute(gemm_mma<64,  false, true >, cudaFuncAttributeMaxDynamicSharedMemorySize, SM64S);

    const int GB = (NN + 127) / 128;   // 782
    const int EG = (NE + 255) / 256;
    const int GG = (NN + 7) / 8;

    // ---- CSR build ----
    zero_kernel<<<(NN/4 + 255)/256, 256>>>((float*)deg, NN/4);
    hist_kernel<<<EG, 256>>>(dst);
    scan_pass1<<<NBLK, 256>>>();
    scan_pass2<<<1, 64>>>();
    scan_pass3<<<NBLK, 256>>>();
    fill_kernel<<<EG, 256>>>(src, dst);

    // ---- W preconvert + zero accumulators ----
    wconv_kernel<<<(5*16384 + 8192 + 255)/256, 256>>>(wA[0], wB[0], wA[1], wB[1], wA[2], wB[2]);
    zero_kernel<<<(NGR * DO_ / 4 + 255)/256, 256>>>(pool, NGR * DO_ / 4);
    zero_kernel<<<1, 32>>>((float*)cnt, NGR / 4);

    // ---- layer 0 ----
    gather_kernel<false><<<GG, 256>>>(x, agg);
    gemm_mma<128, true,  false><<<GB, 256, SM128>>>(agg, whi + 0*32768, wlo + 0*32768, bA[0], hid);
    zero_kernel<<<1, 64>>>(bnst, 64);
    gemm_mma<128, false, true ><<<GB, 256, SM128S>>>(hid, whi + 1*32768, wlo + 1*32768, bB[0], h1);
    bn_finalize_kernel<<<1, 128>>>(gam[0], bet[0], 128);

    // ---- layer 1 ----
    gather_kernel<true><<<GG, 256>>>(h1, agg);
    gemm_mma<128, true,  false><<<GB, 256, SM128>>>(agg, whi + 2*32768, wlo + 2*32768, bA[1], hid);
    zero_kernel<<<1, 64>>>(bnst, 64);
    gemm_mma<128, false, true ><<<GB, 256, SM128S>>>(hid, whi + 3*32768, wlo + 3*32768, bB[1], h2);
    bn_finalize_kernel<<<1, 128>>>(gam[1], bet[1], 128);

    // ---- layer 2 ----
    gather_kernel<true><<<GG, 256>>>(h2, agg);
    gemm_mma<128, true,  false><<<GB, 256, SM128>>>(agg, whi + 4*32768, wlo + 4*32768, bA[2], hid);
    zero_kernel<<<1, 64>>>(bnst, 64);
    gemm_mma<64,  false, true ><<<GB, 256, SM64S>>>(hid, whi + 5*32768, wlo + 5*32768, bB[2], h1);
    bn_finalize_kernel<<<1, 64>>>(gam[2], bet[2], 64);

    // ---- global mean pool (BN+ReLU fused) ----
    pool_sum_kernel<<<(NN * 16 + 255)/256, 256>>>(h1, batch);
    pool_cnt_kernel<<<296, 256>>>(batch);
    pool_fin_kernel<<<(NGR * DO_ + 255)/256, 256>>>((float*)d_out);
}

// round 7
// speedup vs baseline: 1.0126x; 1.0126x over previous
#include <cuda_runtime.h>
#include <cuda_bf16.h>
#include <cstdint>

#define NN   100000
#define NE   1600000
#define NGR  128
#define D_   128
#define DO_  64
#define BN_EPS 1e-5f
#define SCAN_ELEMS 2048
#define NBLK ((NN + SCAN_ELEMS - 1) / SCAN_ELEMS)   // 49

typedef unsigned long long ull;

// ---------------- scratch ----------------
__device__ __align__(16) float g_agg[(size_t)NN * D_];
__device__ __align__(16) float g_hid[(size_t)NN * D_];
__device__ __align__(16) float g_h1 [(size_t)NN * D_];
__device__ __align__(16) float g_h2 [(size_t)NN * D_];
__device__ __align__(16) float g_bnstats[2 * D_];
__device__ __align__(16) float g_scale[D_];
__device__ __align__(16) float g_shift[D_];
__device__ __align__(16) float g_pool[NGR * DO_];
__device__ __align__(16) int   g_cnt[NGR];
// CSR scratch
__device__ __align__(16) int g_deg[NN];
__device__ __align__(16) int g_off[NN + 1];
__device__ __align__(16) int g_cur[NN];
__device__ __align__(16) int g_csr[NE];
__device__ int g_bsum[64];
__device__ int g_bscan[64];
// pre-split, pre-swizzled W images: [k][n] row-major bf16, 16B-chunk XOR swizzle
__device__ __align__(16) unsigned char g_whi[6 * 32768];
__device__ __align__(16) unsigned char g_wlo[6 * 32768];

// ---------------- asm helpers ----------------
__device__ __forceinline__ uint32_t smem_u32(const void* p) {
    uint32_t a;
    asm("{ .reg .u64 t; cvta.to.shared.u64 t, %1; cvt.u32.u64 %0, t; }" : "=r"(a) : "l"(p));
    return a;
}
__device__ __forceinline__ void ldsm_x4(uint32_t& r0, uint32_t& r1, uint32_t& r2, uint32_t& r3,
                                        uint32_t addr) {
    asm volatile("ldmatrix.sync.aligned.m8n8.x4.shared.b16 {%0,%1,%2,%3}, [%4];"
                 : "=r"(r0), "=r"(r1), "=r"(r2), "=r"(r3) : "r"(addr));
}
__device__ __forceinline__ void ldsm_x4t(uint32_t& r0, uint32_t& r1, uint32_t& r2, uint32_t& r3,
                                         uint32_t addr) {
    asm volatile("ldmatrix.sync.aligned.m8n8.x4.trans.shared.b16 {%0,%1,%2,%3}, [%4];"
                 : "=r"(r0), "=r"(r1), "=r"(r2), "=r"(r3) : "r"(addr));
}
__device__ __forceinline__ void mma16816(float* c, uint32_t a0, uint32_t a1, uint32_t a2,
                                         uint32_t a3, uint32_t b0, uint32_t b1) {
    asm volatile("mma.sync.aligned.m16n8k16.row.col.f32.bf16.bf16.f32 "
                 "{%0,%1,%2,%3}, {%4,%5,%6,%7}, {%8,%9}, {%0,%1,%2,%3};"
                 : "+f"(c[0]), "+f"(c[1]), "+f"(c[2]), "+f"(c[3])
                 : "r"(a0), "r"(a1), "r"(a2), "r"(a3), "r"(b0), "r"(b1));
}

// ---------------- utility ----------------
__global__ void zero_kernel(float* __restrict__ p, int n4) {
    int i = blockIdx.x * blockDim.x + threadIdx.x;
    if (i < n4) ((float4*)p)[i] = make_float4(0.f, 0.f, 0.f, 0.f);
}

// ---------------- CSR build ----------------
__global__ void hist_kernel(const int* __restrict__ dst) {
    int i = blockIdx.x * blockDim.x + threadIdx.x;
    if (i < NE) atomicAdd(&g_deg[__ldg(dst + i)], 1);
}
__global__ void scan_pass1() {
    __shared__ int ssum[8];
    int b = blockIdx.x, tid = threadIdx.x;
    int base = b * SCAN_ELEMS + tid * 8;
    int s = 0;
    #pragma unroll
    for (int j = 0; j < 8; j++) { int idx = base + j; s += (idx < NN) ? g_deg[idx] : 0; }
    #pragma unroll
    for (int o = 16; o; o >>= 1) s += __shfl_down_sync(0xffffffffu, s, o);
    if ((tid & 31) == 0) ssum[tid >> 5] = s;
    __syncthreads();
    if (tid == 0) {
        int t = 0;
        #pragma unroll
        for (int i = 0; i < 8; i++) t += ssum[i];
        g_bsum[b] = t;
    }
}
__global__ void scan_pass2() {
    int tid = threadIdx.x;
    int v = (tid < NBLK) ? g_bsum[tid] : 0;
    int incl = v, lane = tid & 31;
    #pragma unroll
    for (int o = 1; o < 32; o <<= 1) {
        int y = __shfl_up_sync(0xffffffffu, incl, o);
        if (lane >= o) incl += y;
    }
    __shared__ int w0;
    if (tid == 31) w0 = incl;
    __syncthreads();
    if (tid >= 32) incl += w0;
    if (tid < 64) g_bscan[tid] = incl - v;
    if (tid == 0) g_off[NN] = NE;
}
__global__ void scan_pass3() {
    int b = blockIdx.x, tid = threadIdx.x;
    int base = b * SCAN_ELEMS + tid * 8;
    int vals[8], t = 0;
    #pragma unroll
    for (int j = 0; j < 8; j++) { vals[j] = (base + j < NN) ? g_deg[base + j] : 0; t += vals[j]; }
    int lane = tid & 31, wid = tid >> 5, incl = t;
    #pragma unroll
    for (int o = 1; o < 32; o <<= 1) {
        int y = __shfl_up_sync(0xffffffffu, incl, o);
        if (lane >= o) incl += y;
    }
    __shared__ int wsum[8], woff[8];
    if (lane == 31) wsum[wid] = incl;
    __syncthreads();
    if (tid == 0) { int a = 0; for (int i = 0; i < 8; i++) { woff[i] = a; a += wsum[i]; } }
    __syncthreads();
    int run = g_bscan[b] + woff[wid] + (incl - t);
    #pragma unroll
    for (int j = 0; j < 8; j++) {
        int idx = base + j;
        if (idx < NN) { g_off[idx] = run; g_cur[idx] = run; run += vals[j]; }
    }
}
__global__ void fill_kernel(const int* __restrict__ src, const int* __restrict__ dst) {
    int i = blockIdx.x * blockDim.x + threadIdx.x;
    if (i < NE) {
        int d = __ldg(dst + i);
        int p = atomicAdd(&g_cur[d], 1);
        g_csr[p] = __ldg(src + i);
    }
}

// ---------------- W split + swizzle preconvert ----------------
__global__ void wconv_kernel(const float* w0, const float* w1, const float* w2,
                             const float* w3, const float* w4, const float* w5)
{
    int i = blockIdx.x * blockDim.x + threadIdx.x;
    if (i >= 5 * 16384 + 8192) return;
    int seg = i >> 14;
    int t = i & 16383;
    int nout = (seg == 5) ? 64 : 128;
    const float* W = (seg == 0) ? w0 : (seg == 1) ? w1 : (seg == 2) ? w2
                   : (seg == 3) ? w3 : (seg == 4) ? w4 : w5;
    int k = t / nout, n = t % nout;
    float w = __ldg(W + k * nout + n);
    __nv_bfloat16 hi = __float2bfloat16(w);
    __nv_bfloat16 lo = __float2bfloat16(w - __bfloat162float(hi));
    int pos = k * nout + ((((n >> 3) ^ (k & 7)) << 3) | (n & 7));
    ((__nv_bfloat16*)(g_whi + seg * 32768))[pos] = hi;
    ((__nv_bfloat16*)(g_wlo + seg * 32768))[pos] = lo;
}

// ---------------- gather (R4-proven 4-edge unroll) ----------------
__device__ __forceinline__ float4 bn_ap(float4 v, float4 sc, float4 sh, bool bn) {
    if (bn) {
        v.x = fmaxf(fmaf(v.x, sc.x, sh.x), 0.f);
        v.y = fmaxf(fmaf(v.y, sc.y, sh.y), 0.f);
        v.z = fmaxf(fmaf(v.z, sc.z, sh.z), 0.f);
        v.w = fmaxf(fmaf(v.w, sc.w, sh.w), 0.f);
    }
    return v;
}
__device__ __forceinline__ void f4acc(float4& a, float4 b) {
    a.x += b.x; a.y += b.y; a.z += b.z; a.w += b.w;
}

template<bool BN>
__global__ void gather_kernel(const float* __restrict__ h, float* __restrict__ out)
{
    int n = blockIdx.x * 8 + (threadIdx.x >> 5);
    if (n >= NN) return;
    int lane = threadIdx.x & 31;
    const float4* __restrict__ h4 = (const float4*)h;

    float4 sc = make_float4(0,0,0,0), sh = make_float4(0,0,0,0);
    if (BN) {
        sc = *(const float4*)(g_scale + lane * 4);
        sh = *(const float4*)(g_shift + lane * 4);
    }
    float4 a0 = bn_ap(__ldg(&h4[(size_t)n * 32 + lane]), sc, sh, BN);
    float4 a1 = make_float4(0,0,0,0), a2 = make_float4(0,0,0,0), a3 = make_float4(0,0,0,0);

    int j = g_off[n], e1 = g_off[n + 1];
    for (; j + 4 <= e1; j += 4) {
        int i0 = __ldg(&g_csr[j]);
        int i1 = __ldg(&g_csr[j + 1]);
        int i2 = __ldg(&g_csr[j + 2]);
        int i3 = __ldg(&g_csr[j + 3]);
        float4 w0 = __ldg(&h4[(size_t)i0 * 32 + lane]);
        float4 w1 = __ldg(&h4[(size_t)i1 * 32 + lane]);
        float4 w2 = __ldg(&h4[(size_t)i2 * 32 + lane]);
        float4 w3 = __ldg(&h4[(size_t)i3 * 32 + lane]);
        f4acc(a0, bn_ap(w0, sc, sh, BN));
        f4acc(a1, bn_ap(w1, sc, sh, BN));
        f4acc(a2, bn_ap(w2, sc, sh, BN));
        f4acc(a3, bn_ap(w3, sc, sh, BN));
    }
    for (; j < e1; j++) {
        int s = __ldg(&g_csr[j]);
        f4acc(a0, bn_ap(__ldg(&h4[(size_t)s * 32 + lane]), sc, sh, BN));
    }
    f4acc(a0, a1); f4acc(a2, a3); f4acc(a0, a2);
    ((float4*)out)[(size_t)n * 32 + lane] = a0;
}

// ---------------- tensor-core GEMM (mma.sync, split-bf16 3-term) ----------------
// out[N,NOUT] = A[N,128] @ W[128,NOUT] + bias ; 256 thr, 128-row tile.
// STATS: fused BN column sum/sumsq accumulation.
template<int NOUT, bool RELU, bool STATS>
__global__ __launch_bounds__(256, 1)
void gemm_mma(const float* __restrict__ A,
              const unsigned char* __restrict__ wh, const unsigned char* __restrict__ wl,
              const float* __restrict__ bias, float* __restrict__ out)
{
    constexpr int NT  = NOUT / 8;       // n8 tiles: 16 or 8
    constexpr int BR  = NOUT * 2;       // B row bytes
    constexpr int AHI = 0;
    constexpr int ALO = 32768;
    constexpr int BHI = 65536;
    constexpr int BLO = 65536 + 128 * BR;
    constexpr int STAT = 65536 + 256 * BR;

    extern __shared__ __align__(16) char smem[];
    const uint32_t sb = smem_u32(smem);
    float* s_sum = (float*)(smem + STAT);
    float* s_sq  = s_sum + NOUT;
    const int tid  = threadIdx.x;
    const int wid  = tid >> 5;
    const int lane = tid & 31;
    const int row0 = blockIdx.x * 128;

    // B tiles: straight copy of pre-swizzled images
    {
        const float4* s1 = (const float4*)wh;
        const float4* s2 = (const float4*)wl;
        float4* d1 = (float4*)(smem + BHI);
        float4* d2 = (float4*)(smem + BLO);
        #pragma unroll
        for (int i = tid; i < NOUT * 16; i += 256) { d1[i] = s1[i]; d2[i] = s2[i]; }
    }
    if (STATS && tid < 2 * NOUT) s_sum[tid] = 0.f;
    // A tile: fp32 -> bf16 hi/lo, swizzled 16B chunks (chunk c at c ^ (r&7))
    for (int i = tid; i < 2048; i += 256) {
        int r = i >> 4, c = i & 15;
        int gr = row0 + r;
        float4 v0 = make_float4(0,0,0,0), v1 = make_float4(0,0,0,0);
        if (gr < NN) {
            const float4* ap = (const float4*)(A + (size_t)gr * 128 + c * 8);
            v0 = __ldg(ap); v1 = __ldg(ap + 1);
        }
        float vv[8] = {v0.x, v0.y, v0.z, v0.w, v1.x, v1.y, v1.z, v1.w};
        uint4 hq, lq;
        uint32_t* hp = (uint32_t*)&hq;
        uint32_t* lp = (uint32_t*)&lq;
        #pragma unroll
        for (int p = 0; p < 4; p++) {
            __nv_bfloat162 h2, l2;
            h2.x = __float2bfloat16(vv[2*p]);
            h2.y = __float2bfloat16(vv[2*p+1]);
            l2.x = __float2bfloat16(vv[2*p]   - __bfloat162float(h2.x));
            l2.y = __float2bfloat16(vv[2*p+1] - __bfloat162float(h2.y));
            hp[p] = *(uint32_t*)&h2;
            lp[p] = *(uint32_t*)&l2;
        }
        uint32_t off = (uint32_t)(r * 256 + ((c ^ (r & 7)) << 4));
        *(uint4*)(smem + AHI + off) = hq;
        *(uint4*)(smem + ALO + off) = lq;
    }
    __syncthreads();

    // mainloop
    const int la = lane & 15;
    const int lb = lane >> 4;
    const int l7 = lane & 7;
    const uint32_t aRow = (uint32_t)((wid * 16 + la) * 256);
    const uint32_t bRow = (uint32_t)(la * BR);

    float acc[NT][4];
    #pragma unroll
    for (int t = 0; t < NT; t++)
        #pragma unroll
        for (int e = 0; e < 4; e++) acc[t][e] = 0.f;

    #pragma unroll 2
    for (int k0 = 0; k0 < 128; k0 += 16) {
        uint32_t kc = (uint32_t)((k0 >> 3) + lb);
        uint32_t aoff = aRow + (((kc ^ (uint32_t)l7)) << 4);
        uint32_t ah0, ah1, ah2, ah3, al0, al1, al2, al3;
        ldsm_x4(ah0, ah1, ah2, ah3, sb + AHI + aoff);
        ldsm_x4(al0, al1, al2, al3, sb + ALO + aoff);
        uint32_t bbase = (uint32_t)(k0 * BR) + bRow;
        #pragma unroll
        for (int nt = 0; nt < NT; nt += 2) {
            uint32_t boff = bbase + ((((uint32_t)(nt + lb)) ^ (uint32_t)l7) << 4);
            uint32_t bh0, bh1, bh2, bh3, bl0, bl1, bl2, bl3;
            ldsm_x4t(bh0, bh1, bh2, bh3, sb + BHI + boff);
            ldsm_x4t(bl0, bl1, bl2, bl3, sb + BLO + boff);
            mma16816(acc[nt],     ah0, ah1, ah2, ah3, bh0, bh1);
            mma16816(acc[nt + 1], ah0, ah1, ah2, ah3, bh2, bh3);
            mma16816(acc[nt],     ah0, ah1, ah2, ah3, bl0, bl1);
            mma16816(acc[nt + 1], ah0, ah1, ah2, ah3, bl2, bl3);
            mma16816(acc[nt],     al0, al1, al2, al3, bh0, bh1);
            mma16816(acc[nt + 1], al0, al1, al2, al3, bh2, bh3);
        }
    }

    // epilogue: lane l -> rows (l/4, l/4+8), cols 2*(l%4)+... per n8 tile
    int r1 = row0 + wid * 16 + (lane >> 2);
    int r2 = r1 + 8;
    #pragma unroll
    for (int nt = 0; nt < NT; nt++) {
        int col = nt * 8 + (lane & 3) * 2;
        float2 bb = __ldg((const float2*)(bias + col));
        float v0 = acc[nt][0] + bb.x;
        float v1 = acc[nt][1] + bb.y;
        float v2 = acc[nt][2] + bb.x;
        float v3 = acc[nt][3] + bb.y;
        if (RELU) {
            v0 = fmaxf(v0, 0.f); v1 = fmaxf(v1, 0.f);
            v2 = fmaxf(v2, 0.f); v3 = fmaxf(v3, 0.f);
        }
        if (STATS) {
            float cs0 = 0.f, cs1 = 0.f, cq0 = 0.f, cq1 = 0.f;
            if (r1 < NN) {
                *(float2*)(out + (size_t)r1 * NOUT + col) = make_float2(v0, v1);
                cs0 += v0; cs1 += v1; cq0 += v0 * v0; cq1 += v1 * v1;
            }
            if (r2 < NN) {
                *(float2*)(out + (size_t)r2 * NOUT + col) = make_float2(v2, v3);
                cs0 += v2; cs1 += v3; cq0 += v2 * v2; cq1 += v3 * v3;
            }
            atomicAdd(&s_sum[col],     cs0);
            atomicAdd(&s_sum[col + 1], cs1);
            atomicAdd(&s_sq[col],      cq0);
            atomicAdd(&s_sq[col + 1],  cq1);
        } else {
            if (r1 < NN) *(float2*)(out + (size_t)r1 * NOUT + col) = make_float2(v0, v1);
            if (r2 < NN) *(float2*)(out + (size_t)r2 * NOUT + col) = make_float2(v2, v3);
        }
    }
    if (STATS) {
        __syncthreads();
        if (tid < NOUT) {
            atomicAdd(&g_bnstats[tid], s_sum[tid]);
            atomicAdd(&g_bnstats[NOUT + tid], s_sq[tid]);
        }
    }
}

// ---------------- BN finalize ----------------
__global__ void bn_finalize_kernel(const float* __restrict__ gamma,
                                   const float* __restrict__ beta, int nout)
{
    int c = threadIdx.x;
    if (c < nout) {
        const float invN = 1.0f / (float)NN;
        float mu  = g_bnstats[c] * invN;
        float var = g_bnstats[nout + c] * invN - mu * mu;
        float s   = gamma[c] * rsqrtf(var + BN_EPS);
        g_scale[c] = s;
        g_shift[c] = beta[c] - mu * s;
    }
}

// ---------------- pooling (BN+ReLU fused) ----------------
__global__ void pool_sum_kernel(const float* __restrict__ pre, const int* __restrict__ batch)
{
    int t = blockIdx.x * blockDim.x + threadIdx.x;
    if (t >= NN * 16) return;
    int n = t >> 4, q = t & 15;
    int c = q << 2;
    int b = __ldg(batch + n);
    float4 v  = *(const float4*)(pre + (size_t)n * DO_ + c);
    float4 sc = *(const float4*)(g_scale + c);
    float4 sh = *(const float4*)(g_shift + c);
    v.x = fmaxf(fmaf(v.x, sc.x, sh.x), 0.f);
    v.y = fmaxf(fmaf(v.y, sc.y, sh.y), 0.f);
    v.z = fmaxf(fmaf(v.z, sc.z, sh.z), 0.f);
    v.w = fmaxf(fmaf(v.w, sc.w, sh.w), 0.f);
    float* p = g_pool + b * DO_ + c;
    asm volatile("red.global.add.v4.f32 [%0], {%1, %2, %3, %4};"
                 :: "l"(p), "f"(v.x), "f"(v.y), "f"(v.z), "f"(v.w) : "memory");
}

__global__ void pool_cnt_kernel(const int* __restrict__ batch)
{
    __shared__ int sc[NGR];
    for (int i = threadIdx.x; i < NGR; i += blockDim.x) sc[i] = 0;
    __syncthreads();
    for (int i = blockIdx.x * blockDim.x + threadIdx.x; i < NN; i += gridDim.x * blockDim.x)
        atomicAdd(&sc[__ldg(batch + i)], 1);
    __syncthreads();
    for (int i = threadIdx.x; i < NGR; i += blockDim.x)
        if (sc[i]) atomicAdd(&g_cnt[i], sc[i]);
}

__global__ void pool_fin_kernel(float* __restrict__ out)
{
    int i = blockIdx.x * blockDim.x + threadIdx.x;
    if (i < NGR * DO_) {
        int g = i >> 6;
        float c = (float)(g_cnt[g] > 0 ? g_cnt[g] : 1);
        out[i] = g_pool[i] / c;
    }
}

// ---------------- launcher ----------------
extern "C" void kernel_launch(void* const* d_in, const int* in_sizes, int n_in,
                              void* d_out, int out_size)
{
    const float* x     = (const float*)d_in[0];
    const int*   ei    = (const int*)d_in[1];
    const int*   batch = (const int*)d_in[2];
    const float *wA[3], *bA[3], *wB[3], *bB[3], *gam[3], *bet[3];
    for (int l = 0; l < 3; l++) {
        wA[l]  = (const float*)d_in[3 + 6*l + 0];
        bA[l]  = (const float*)d_in[3 + 6*l + 1];
        wB[l]  = (const float*)d_in[3 + 6*l + 2];
        bB[l]  = (const float*)d_in[3 + 6*l + 3];
        gam[l] = (const float*)d_in[3 + 6*l + 4];
        bet[l] = (const float*)d_in[3 + 6*l + 5];
    }
    const int* src = ei;
    const int* dst = ei + NE;

    float *agg, *hid, *h1, *h2, *bnst, *pool;
    int *cnt, *deg;
    unsigned char *whi, *wlo;
    cudaGetSymbolAddress((void**)&agg,  g_agg);
    cudaGetSymbolAddress((void**)&hid,  g_hid);
    cudaGetSymbolAddress((void**)&h1,   g_h1);
    cudaGetSymbolAddress((void**)&h2,   g_h2);
    cudaGetSymbolAddress((void**)&bnst, g_bnstats);
    cudaGetSymbolAddress((void**)&pool, g_pool);
    cudaGetSymbolAddress((void**)&cnt,  g_cnt);
    cudaGetSymbolAddress((void**)&deg,  g_deg);
    cudaGetSymbolAddress((void**)&whi,  g_whi);
    cudaGetSymbolAddress((void**)&wlo,  g_wlo);

    constexpr int SM128  = 65536 + 2 * 128 * 256;            // 131072 (no stats)
    constexpr int SM128S = 65536 + 2 * 128 * 256 + 1024;     // 132096 (stats)
    constexpr int SM64S  = 65536 + 2 * 64  * 256 + 512;      //  98816 (stats)
    cudaFuncSetAttribute(gemm_mma<128, true,  false>, cudaFuncAttributeMaxDynamicSharedMemorySize, SM128);
    cudaFuncSetAttribute(gemm_mma<128, false, true >, cudaFuncAttributeMaxDynamicSharedMemorySize, SM128S);
    cudaFuncSetAttribute(gemm_mma<64,  false, true >, cudaFuncAttributeMaxDynamicSharedMemorySize, SM64S);

    const int GB = (NN + 127) / 128;   // 782
    const int EG = (NE + 255) / 256;
    const int GG = (NN + 7) / 8;

    // ---- CSR build ----
    zero_kernel<<<(NN/4 + 255)/256, 256>>>((float*)deg, NN/4);
    hist_kernel<<<EG, 256>>>(dst);
    scan_pass1<<<NBLK, 256>>>();
    scan_pass2<<<1, 64>>>();
    scan_pass3<<<NBLK, 256>>>();
    fill_kernel<<<EG, 256>>>(src, dst);

    // ---- W preconvert + zero accumulators ----
    wconv_kernel<<<(5*16384 + 8192 + 255)/256, 256>>>(wA[0], wB[0], wA[1], wB[1], wA[2], wB[2]);
    zero_kernel<<<(NGR * DO_ / 4 + 255)/256, 256>>>(pool, NGR * DO_ / 4);
    zero_kernel<<<1, 32>>>((float*)cnt, NGR / 4);

    // ---- layer 0 ----
    gather_kernel<false><<<GG, 256>>>(x, agg);
    gemm_mma<128, true,  false><<<GB, 256, SM128>>>(agg, whi + 0*32768, wlo + 0*32768, bA[0], hid);
    zero_kernel<<<1, 64>>>(bnst, 64);
    gemm_mma<128, false, true ><<<GB, 256, SM128S>>>(hid, whi + 1*32768, wlo + 1*32768, bB[0], h1);
    bn_finalize_kernel<<<1, 128>>>(gam[0], bet[0], 128);

    // ---- layer 1 ----
    gather_kernel<true><<<GG, 256>>>(h1, agg);
    gemm_mma<128, true,  false><<<GB, 256, SM128>>>(agg, whi + 2*32768, wlo + 2*32768, bA[1], hid);
    zero_kernel<<<1, 64>>>(bnst, 64);
    gemm_mma<128, false, true ><<<GB, 256, SM128S>>>(hid, whi + 3*32768, wlo + 3*32768, bB[1], h2);
    bn_finalize_kernel<<<1, 128>>>(gam[1], bet[1], 128);

    // ---- layer 2 ----
    gather_kernel<true><<<GG, 256>>>(h2, agg);
    gemm_mma<128, true,  false><<<GB, 256, SM128>>>(agg, whi + 4*32768, wlo + 4*32768, bA[2], hid);
    zero_kernel<<<1, 64>>>(bnst, 64);
    gemm_mma<64,  false, true ><<<GB, 256, SM64S>>>(hid, whi + 5*32768, wlo + 5*32768, bB[2], h1);
    bn_finalize_kernel<<<1, 64>>>(gam[2], bet[2], 64);

    // ---- global mean pool (BN+ReLU fused) ----
    pool_sum_kernel<<<(NN * 16 + 255)/256, 256>>>(h1, batch);
    pool_cnt_kernel<<<296, 256>>>(batch);
    pool_fin_kernel<<<(NGR * DO_ + 255)/256, 256>>>((float*)d_out);
}

// round 8
// speedup vs baseline: 1.4988x; 1.4801x over previous
#include <cuda_runtime.h>
#include <cuda_bf16.h>
#include <cstdint>

#define NN   100000
#define NE   1600000
#define NGR  128
#define D_   128
#define DO_  64
#define BN_EPS 1e-5f
#define SCAN_ELEMS 2048
#define NBLK ((NN + SCAN_ELEMS - 1) / SCAN_ELEMS)   // 49

typedef unsigned long long ull;

// ---------------- scratch ----------------
__device__ __align__(16) float g_agg[(size_t)NN * D_];
__device__ __align__(16) float g_hid[(size_t)NN * D_];
__device__ __align__(16) float g_h1 [(size_t)NN * D_];
__device__ __align__(16) float g_h2 [(size_t)NN * D_];
__device__ __align__(16) float g_bnstats[2 * D_];   // zero at module init; finalize re-zeroes
__device__ __align__(16) float g_scale[D_];
__device__ __align__(16) float g_shift[D_];
__device__ __align__(16) float g_pool[NGR * DO_];
__device__ __align__(16) int   g_cnt[NGR];
// CSR scratch
__device__ __align__(16) int g_deg[NN];             // zero at init; scan3 re-zeroes
__device__ __align__(16) int g_off[NN + 1];
__device__ __align__(16) int g_cur[NN];
__device__ __align__(16) int g_csr[NE];
__device__ int g_bsum[64];
__device__ int g_bscan[64];
// pre-split, pre-swizzled W images: [k][n] row-major bf16, 16B-chunk XOR swizzle
__device__ __align__(16) unsigned char g_whi[6 * 32768];
__device__ __align__(16) unsigned char g_wlo[6 * 32768];

// ---------------- asm helpers ----------------
__device__ __forceinline__ uint32_t smem_u32(const void* p) {
    uint32_t a;
    asm("{ .reg .u64 t; cvta.to.shared.u64 t, %1; cvt.u32.u64 %0, t; }" : "=r"(a) : "l"(p));
    return a;
}
__device__ __forceinline__ void ldsm_x4(uint32_t& r0, uint32_t& r1, uint32_t& r2, uint32_t& r3,
                                        uint32_t addr) {
    asm volatile("ldmatrix.sync.aligned.m8n8.x4.shared.b16 {%0,%1,%2,%3}, [%4];"
                 : "=r"(r0), "=r"(r1), "=r"(r2), "=r"(r3) : "r"(addr));
}
__device__ __forceinline__ void ldsm_x4t(uint32_t& r0, uint32_t& r1, uint32_t& r2, uint32_t& r3,
                                         uint32_t addr) {
    asm volatile("ldmatrix.sync.aligned.m8n8.x4.trans.shared.b16 {%0,%1,%2,%3}, [%4];"
                 : "=r"(r0), "=r"(r1), "=r"(r2), "=r"(r3) : "r"(addr));
}
__device__ __forceinline__ void mma16816(float* c, uint32_t a0, uint32_t a1, uint32_t a2,
                                         uint32_t a3, uint32_t b0, uint32_t b1) {
    asm volatile("mma.sync.aligned.m16n8k16.row.col.f32.bf16.bf16.f32 "
                 "{%0,%1,%2,%3}, {%4,%5,%6,%7}, {%8,%9}, {%0,%1,%2,%3};"
                 : "+f"(c[0]), "+f"(c[1]), "+f"(c[2]), "+f"(c[3])
                 : "r"(a0), "r"(a1), "r"(a2), "r"(a3), "r"(b0), "r"(b1));
}

// ---------------- CSR build ----------------
__global__ void hist_kernel(const int* __restrict__ dst) {
    int i = blockIdx.x * blockDim.x + threadIdx.x;
    if (i < NE) atomicAdd(&g_deg[__ldg(dst + i)], 1);
}
__global__ void scan_pass1() {
    __shared__ int ssum[8];
    int b = blockIdx.x, tid = threadIdx.x;
    int base = b * SCAN_ELEMS + tid * 8;
    int s = 0;
    #pragma unroll
    for (int j = 0; j < 8; j++) { int idx = base + j; s += (idx < NN) ? g_deg[idx] : 0; }
    #pragma unroll
    for (int o = 16; o; o >>= 1) s += __shfl_down_sync(0xffffffffu, s, o);
    if ((tid & 31) == 0) ssum[tid >> 5] = s;
    __syncthreads();
    if (tid == 0) {
        int t = 0;
        #pragma unroll
        for (int i = 0; i < 8; i++) t += ssum[i];
        g_bsum[b] = t;
    }
}
__global__ void scan_pass2() {
    int tid = threadIdx.x;
    int v = (tid < NBLK) ? g_bsum[tid] : 0;
    int incl = v, lane = tid & 31;
    #pragma unroll
    for (int o = 1; o < 32; o <<= 1) {
        int y = __shfl_up_sync(0xffffffffu, incl, o);
        if (lane >= o) incl += y;
    }
    __shared__ int w0;
    if (tid == 31) w0 = incl;
    __syncthreads();
    if (tid >= 32) incl += w0;
    if (tid < 64) g_bscan[tid] = incl - v;
    if (tid == 0) g_off[NN] = NE;
}
__global__ void scan_pass3() {
    int b = blockIdx.x, tid = threadIdx.x;
    int base = b * SCAN_ELEMS + tid * 8;
    int vals[8], t = 0;
    #pragma unroll
    for (int j = 0; j < 8; j++) { vals[j] = (base + j < NN) ? g_deg[base + j] : 0; t += vals[j]; }
    int lane = tid & 31, wid = tid >> 5, incl = t;
    #pragma unroll
    for (int o = 1; o < 32; o <<= 1) {
        int y = __shfl_up_sync(0xffffffffu, incl, o);
        if (lane >= o) incl += y;
    }
    __shared__ int wsum[8], woff[8];
    if (lane == 31) wsum[wid] = incl;
    __syncthreads();
    if (tid == 0) { int a = 0; for (int i = 0; i < 8; i++) { woff[i] = a; a += wsum[i]; } }
    __syncthreads();
    int run = g_bscan[b] + woff[wid] + (incl - t);
    #pragma unroll
    for (int j = 0; j < 8; j++) {
        int idx = base + j;
        if (idx < NN) {
            g_off[idx] = run; g_cur[idx] = run; run += vals[j];
            g_deg[idx] = 0;   // reset for next replay (read above)
        }
    }
}
__global__ void fill_kernel(const int* __restrict__ src, const int* __restrict__ dst) {
    int i = blockIdx.x * blockDim.x + threadIdx.x;
    if (i < NE) {
        int d = __ldg(dst + i);
        int p = atomicAdd(&g_cur[d], 1);
        g_csr[p] = __ldg(src + i);
    }
}

// ---------------- W split + swizzle preconvert (+ pool/cnt zeroing) ----------------
__global__ void wconv_kernel(const float* w0, const float* w1, const float* w2,
                             const float* w3, const float* w4, const float* w5)
{
    int i = blockIdx.x * blockDim.x + threadIdx.x;
    if (i < NGR * DO_) g_pool[i] = 0.f;        // zero pool accumulators for this replay
    if (i < NGR) g_cnt[i] = 0;
    if (i >= 5 * 16384 + 8192) return;
    int seg = i >> 14;
    int t = i & 16383;
    int nout = (seg == 5) ? 64 : 128;
    const float* W = (seg == 0) ? w0 : (seg == 1) ? w1 : (seg == 2) ? w2
                   : (seg == 3) ? w3 : (seg == 4) ? w4 : w5;
    int k = t / nout, n = t % nout;
    float w = __ldg(W + k * nout + n);
    __nv_bfloat16 hi = __float2bfloat16(w);
    __nv_bfloat16 lo = __float2bfloat16(w - __bfloat162float(hi));
    int pos = k * nout + ((((n >> 3) ^ (k & 7)) << 3) | (n & 7));
    ((__nv_bfloat16*)(g_whi + seg * 32768))[pos] = hi;
    ((__nv_bfloat16*)(g_wlo + seg * 32768))[pos] = lo;
}

// ---------------- gather (R4-proven 4-edge unroll, int4 index loads) ----------------
__device__ __forceinline__ float4 bn_ap(float4 v, float4 sc, float4 sh, bool bn) {
    if (bn) {
        v.x = fmaxf(fmaf(v.x, sc.x, sh.x), 0.f);
        v.y = fmaxf(fmaf(v.y, sc.y, sh.y), 0.f);
        v.z = fmaxf(fmaf(v.z, sc.z, sh.z), 0.f);
        v.w = fmaxf(fmaf(v.w, sc.w, sh.w), 0.f);
    }
    return v;
}
__device__ __forceinline__ void f4acc(float4& a, float4 b) {
    a.x += b.x; a.y += b.y; a.z += b.z; a.w += b.w;
}

template<bool BN>
__global__ void gather_kernel(const float* __restrict__ h, float* __restrict__ out)
{
    int n = blockIdx.x * 8 + (threadIdx.x >> 5);
    if (n >= NN) return;
    int lane = threadIdx.x & 31;
    const float4* __restrict__ h4 = (const float4*)h;

    float4 sc = make_float4(0,0,0,0), sh = make_float4(0,0,0,0);
    if (BN) {
        sc = *(const float4*)(g_scale + lane * 4);
        sh = *(const float4*)(g_shift + lane * 4);
    }
    float4 a0 = bn_ap(__ldg(&h4[(size_t)n * 32 + lane]), sc, sh, BN);
    float4 a1 = make_float4(0,0,0,0), a2 = make_float4(0,0,0,0), a3 = make_float4(0,0,0,0);

    int j = g_off[n], e1 = g_off[n + 1];
    // prologue to 4-alignment
    for (; j < e1 && (j & 3); j++) {
        int s = __ldg(&g_csr[j]);
        f4acc(a0, bn_ap(__ldg(&h4[(size_t)s * 32 + lane]), sc, sh, BN));
    }
    // aligned body: one int4 broadcast load carries 4 indices
    for (; j + 4 <= e1; j += 4) {
        int4 q = __ldg((const int4*)(g_csr + j));
        float4 w0 = __ldg(&h4[(size_t)q.x * 32 + lane]);
        float4 w1 = __ldg(&h4[(size_t)q.y * 32 + lane]);
        float4 w2 = __ldg(&h4[(size_t)q.z * 32 + lane]);
        float4 w3 = __ldg(&h4[(size_t)q.w * 32 + lane]);
        f4acc(a0, bn_ap(w0, sc, sh, BN));
        f4acc(a1, bn_ap(w1, sc, sh, BN));
        f4acc(a2, bn_ap(w2, sc, sh, BN));
        f4acc(a3, bn_ap(w3, sc, sh, BN));
    }
    for (; j < e1; j++) {
        int s = __ldg(&g_csr[j]);
        f4acc(a0, bn_ap(__ldg(&h4[(size_t)s * 32 + lane]), sc, sh, BN));
    }
    f4acc(a0, a1); f4acc(a2, a3); f4acc(a0, a2);
    ((float4*)out)[(size_t)n * 32 + lane] = a0;
}

// ---------------- tensor-core GEMM (mma.sync, split-bf16 3-term) — R4 version ----------------
template<int NOUT, bool RELU>
__global__ __launch_bounds__(256, 1)
void gemm_mma(const float* __restrict__ A,
              const unsigned char* __restrict__ wh, const unsigned char* __restrict__ wl,
              const float* __restrict__ bias, float* __restrict__ out)
{
    constexpr int NT  = NOUT / 8;       // n8 tiles: 16 or 8
    constexpr int BR  = NOUT * 2;       // B row bytes
    constexpr int AHI = 0;
    constexpr int ALO = 32768;
    constexpr int BHI = 65536;
    constexpr int BLO = 65536 + 128 * BR;

    extern __shared__ __align__(16) char smem[];
    const uint32_t sb = smem_u32(smem);
    const int tid  = threadIdx.x;
    const int wid  = tid >> 5;
    const int lane = tid & 31;
    const int row0 = blockIdx.x * 128;

    // B tiles: straight copy of pre-swizzled images
    {
        const float4* s1 = (const float4*)wh;
        const float4* s2 = (const float4*)wl;
        float4* d1 = (float4*)(smem + BHI);
        float4* d2 = (float4*)(smem + BLO);
        #pragma unroll
        for (int i = tid; i < NOUT * 16; i += 256) { d1[i] = s1[i]; d2[i] = s2[i]; }
    }
    // A tile: fp32 -> bf16 hi/lo, swizzled 16B chunks (chunk c at c ^ (r&7))
    for (int i = tid; i < 2048; i += 256) {
        int r = i >> 4, c = i & 15;
        int gr = row0 + r;
        float4 v0 = make_float4(0,0,0,0), v1 = make_float4(0,0,0,0);
        if (gr < NN) {
            const float4* ap = (const float4*)(A + (size_t)gr * 128 + c * 8);
            v0 = __ldg(ap); v1 = __ldg(ap + 1);
        }
        float vv[8] = {v0.x, v0.y, v0.z, v0.w, v1.x, v1.y, v1.z, v1.w};
        uint4 hq, lq;
        uint32_t* hp = (uint32_t*)&hq;
        uint32_t* lp = (uint32_t*)&lq;
        #pragma unroll
        for (int p = 0; p < 4; p++) {
            __nv_bfloat162 h2, l2;
            h2.x = __float2bfloat16(vv[2*p]);
            h2.y = __float2bfloat16(vv[2*p+1]);
            l2.x = __float2bfloat16(vv[2*p]   - __bfloat162float(h2.x));
            l2.y = __float2bfloat16(vv[2*p+1] - __bfloat162float(h2.y));
            hp[p] = *(uint32_t*)&h2;
            lp[p] = *(uint32_t*)&l2;
        }
        uint32_t off = (uint32_t)(r * 256 + ((c ^ (r & 7)) << 4));
        *(uint4*)(smem + AHI + off) = hq;
        *(uint4*)(smem + ALO + off) = lq;
    }
    __syncthreads();

    // mainloop
    const int la = lane & 15;
    const int lb = lane >> 4;
    const int l7 = lane & 7;
    const uint32_t aRow = (uint32_t)((wid * 16 + la) * 256);
    const uint32_t bRow = (uint32_t)(la * BR);

    float acc[NT][4];
    #pragma unroll
    for (int t = 0; t < NT; t++)
        #pragma unroll
        for (int e = 0; e < 4; e++) acc[t][e] = 0.f;

    #pragma unroll 2
    for (int k0 = 0; k0 < 128; k0 += 16) {
        uint32_t kc = (uint32_t)((k0 >> 3) + lb);
        uint32_t aoff = aRow + (((kc ^ (uint32_t)l7)) << 4);
        uint32_t ah0, ah1, ah2, ah3, al0, al1, al2, al3;
        ldsm_x4(ah0, ah1, ah2, ah3, sb + AHI + aoff);
        ldsm_x4(al0, al1, al2, al3, sb + ALO + aoff);
        uint32_t bbase = (uint32_t)(k0 * BR) + bRow;
        #pragma unroll
        for (int nt = 0; nt < NT; nt += 2) {
            uint32_t boff = bbase + ((((uint32_t)(nt + lb)) ^ (uint32_t)l7) << 4);
            uint32_t bh0, bh1, bh2, bh3, bl0, bl1, bl2, bl3;
            ldsm_x4t(bh0, bh1, bh2, bh3, sb + BHI + boff);
            ldsm_x4t(bl0, bl1, bl2, bl3, sb + BLO + boff);
            mma16816(acc[nt],     ah0, ah1, ah2, ah3, bh0, bh1);
            mma16816(acc[nt + 1], ah0, ah1, ah2, ah3, bh2, bh3);
            mma16816(acc[nt],     ah0, ah1, ah2, ah3, bl0, bl1);
            mma16816(acc[nt + 1], ah0, ah1, ah2, ah3, bl2, bl3);
            mma16816(acc[nt],     al0, al1, al2, al3, bh0, bh1);
            mma16816(acc[nt + 1], al0, al1, al2, al3, bh2, bh3);
        }
    }

    // epilogue
    int r1 = row0 + wid * 16 + (lane >> 2);
    int r2 = r1 + 8;
    #pragma unroll
    for (int nt = 0; nt < NT; nt++) {
        int col = nt * 8 + (lane & 3) * 2;
        float2 bb = __ldg((const float2*)(bias + col));
        float v0 = acc[nt][0] + bb.x;
        float v1 = acc[nt][1] + bb.y;
        float v2 = acc[nt][2] + bb.x;
        float v3 = acc[nt][3] + bb.y;
        if (RELU) {
            v0 = fmaxf(v0, 0.f); v1 = fmaxf(v1, 0.f);
            v2 = fmaxf(v2, 0.f); v3 = fmaxf(v3, 0.f);
        }
        if (r1 < NN) *(float2*)(out + (size_t)r1 * NOUT + col) = make_float2(v0, v1);
        if (r2 < NN) *(float2*)(out + (size_t)r2 * NOUT + col) = make_float2(v2, v3);
    }
}

// ---------------- BN column stats (R4 version) ----------------
template<int NOUT>
__global__ void stats_kernel(const float* __restrict__ h)
{
    constexpr int QC = NOUT / 4;
    constexpr int STEP = 256 / QC;
    __shared__ float ss[NOUT], sq[NOUT];
    int tid = threadIdx.x;
    if (tid < NOUT) { ss[tid] = 0.f; sq[tid] = 0.f; }
    __syncthreads();
    int qc = tid % QC, rg = tid / QC;
    int rend = min(blockIdx.x * 512 + 512, NN);
    float4 s4 = make_float4(0,0,0,0), q4 = make_float4(0,0,0,0);
    for (int r = blockIdx.x * 512 + rg; r < rend; r += STEP) {
        float4 v = __ldg((const float4*)(h + (size_t)r * NOUT) + qc);
        s4.x += v.x; s4.y += v.y; s4.z += v.z; s4.w += v.w;
        q4.x += v.x*v.x; q4.y += v.y*v.y; q4.z += v.z*v.z; q4.w += v.w*v.w;
    }
    int c = qc * 4;
    atomicAdd(&ss[c+0], s4.x); atomicAdd(&ss[c+1], s4.y);
    atomicAdd(&ss[c+2], s4.z); atomicAdd(&ss[c+3], s4.w);
    atomicAdd(&sq[c+0], q4.x); atomicAdd(&sq[c+1], q4.y);
    atomicAdd(&sq[c+2], q4.z); atomicAdd(&sq[c+3], q4.w);
    __syncthreads();
    if (tid < NOUT) {
        atomicAdd(&g_bnstats[tid], ss[tid]);
        atomicAdd(&g_bnstats[NOUT + tid], sq[tid]);
    }
}

// ---------------- BN finalize (resets stats after read) ----------------
__global__ void bn_finalize_kernel(const float* __restrict__ gamma,
                                   const float* __restrict__ beta, int nout)
{
    int c = threadIdx.x;
    if (c < nout) {
        const float invN = 1.0f / (float)NN;
        float sv = g_bnstats[c];
        float qv = g_bnstats[nout + c];
        float mu  = sv * invN;
        float var = qv * invN - mu * mu;
        float s   = gamma[c] * rsqrtf(var + BN_EPS);
        g_scale[c] = s;
        g_shift[c] = beta[c] - mu * s;
        g_bnstats[c] = 0.f;            // reset for next use (per-thread, race-free)
        g_bnstats[nout + c] = 0.f;
    }
}

// ---------------- pooling (BN+ReLU fused) ----------------
__global__ void pool_sum_kernel(const float* __restrict__ pre, const int* __restrict__ batch)
{
    int t = blockIdx.x * blockDim.x + threadIdx.x;
    if (t >= NN * 16) return;
    int n = t >> 4, q = t & 15;
    int c = q << 2;
    int b = __ldg(batch + n);
    float4 v  = *(const float4*)(pre + (size_t)n * DO_ + c);
    float4 sc = *(const float4*)(g_scale + c);
    float4 sh = *(const float4*)(g_shift + c);
    v.x = fmaxf(fmaf(v.x, sc.x, sh.x), 0.f);
    v.y = fmaxf(fmaf(v.y, sc.y, sh.y), 0.f);
    v.z = fmaxf(fmaf(v.z, sc.z, sh.z), 0.f);
    v.w = fmaxf(fmaf(v.w, sc.w, sh.w), 0.f);
    float* p = g_pool + b * DO_ + c;
    asm volatile("red.global.add.v4.f32 [%0], {%1, %2, %3, %4};"
                 :: "l"(p), "f"(v.x), "f"(v.y), "f"(v.z), "f"(v.w) : "memory");
}

__global__ void pool_cnt_kernel(const int* __restrict__ batch)
{
    __shared__ int sc[NGR];
    for (int i = threadIdx.x; i < NGR; i += blockDim.x) sc[i] = 0;
    __syncthreads();
    for (int i = blockIdx.x * blockDim.x + threadIdx.x; i < NN; i += gridDim.x * blockDim.x)
        atomicAdd(&sc[__ldg(batch + i)], 1);
    __syncthreads();
    for (int i = threadIdx.x; i < NGR; i += blockDim.x)
        if (sc[i]) atomicAdd(&g_cnt[i], sc[i]);
}

__global__ void pool_fin_kernel(float* __restrict__ out)
{
    int i = blockIdx.x * blockDim.x + threadIdx.x;
    if (i < NGR * DO_) {
        int g = i >> 6;
        float c = (float)(g_cnt[g] > 0 ? g_cnt[g] : 1);
        out[i] = g_pool[i] / c;
    }
}

// ---------------- launcher ----------------
extern "C" void kernel_launch(void* const* d_in, const int* in_sizes, int n_in,
                              void* d_out, int out_size)
{
    const float* x     = (const float*)d_in[0];
    const int*   ei    = (const int*)d_in[1];
    const int*   batch = (const int*)d_in[2];
    const float *wA[3], *bA[3], *wB[3], *bB[3], *gam[3], *bet[3];
    for (int l = 0; l < 3; l++) {
        wA[l]  = (const float*)d_in[3 + 6*l + 0];
        bA[l]  = (const float*)d_in[3 + 6*l + 1];
        wB[l]  = (const float*)d_in[3 + 6*l + 2];
        bB[l]  = (const float*)d_in[3 + 6*l + 3];
        gam[l] = (const float*)d_in[3 + 6*l + 4];
        bet[l] = (const float*)d_in[3 + 6*l + 5];
    }
    const int* src = ei;
    const int* dst = ei + NE;

    float *agg, *hid, *h1, *h2;
    unsigned char *whi, *wlo;
    cudaGetSymbolAddress((void**)&agg,  g_agg);
    cudaGetSymbolAddress((void**)&hid,  g_hid);
    cudaGetSymbolAddress((void**)&h1,   g_h1);
    cudaGetSymbolAddress((void**)&h2,   g_h2);
    cudaGetSymbolAddress((void**)&whi,  g_whi);
    cudaGetSymbolAddress((void**)&wlo,  g_wlo);

    constexpr int SM128 = 65536 + 2 * 128 * 256;  // 131072
    constexpr int SM64  = 65536 + 2 * 64  * 256;  //  98304
    cudaFuncSetAttribute(gemm_mma<128, true >, cudaFuncAttributeMaxDynamicSharedMemorySize, SM128);
    cudaFuncSetAttribute(gemm_mma<128, false>, cudaFuncAttributeMaxDynamicSharedMemorySize, SM128);
    cudaFuncSetAttribute(gemm_mma<64,  false>, cudaFuncAttributeMaxDynamicSharedMemorySize, SM64);

    const int GB = (NN + 127) / 128;   // 782
    const int EG = (NE + 255) / 256;
    const int GG = (NN + 7) / 8;
    const int SG = (NN + 511) / 512;

    // ---- CSR build (g_deg zeroed by previous replay's scan_pass3 / module init) ----
    hist_kernel<<<EG, 256>>>(dst);
    scan_pass1<<<NBLK, 256>>>();
    scan_pass2<<<1, 64>>>();
    scan_pass3<<<NBLK, 256>>>();
    fill_kernel<<<EG, 256>>>(src, dst);

    // ---- W preconvert (+ pool/cnt zeroing) ----
    wconv_kernel<<<(5*16384 + 8192 + 255)/256, 256>>>(wA[0], wB[0], wA[1], wB[1], wA[2], wB[2]);

    // ---- layer 0 ----
    gather_kernel<false><<<GG, 256>>>(x, agg);
    gemm_mma<128, true ><<<GB, 256, SM128>>>(agg, whi + 0*32768, wlo + 0*32768, bA[0], hid);
    gemm_mma<128, false><<<GB, 256, SM128>>>(hid, whi + 1*32768, wlo + 1*32768, bB[0], h1);
    stats_kernel<128><<<SG, 256>>>(h1);
    bn_finalize_kernel<<<1, 128>>>(gam[0], bet[0], 128);

    // ---- layer 1 ----
    gather_kernel<true><<<GG, 256>>>(h1, agg);
    gemm_mma<128, true ><<<GB, 256, SM128>>>(agg, whi + 2*32768, wlo + 2*32768, bA[1], hid);
    gemm_mma<128, false><<<GB, 256, SM128>>>(hid, whi + 3*32768, wlo + 3*32768, bB[1], h2);
    stats_kernel<128><<<SG, 256>>>(h2);
    bn_finalize_kernel<<<1, 128>>>(gam[1], bet[1], 128);

    // ---- layer 2 ----
    gather_kernel<true><<<GG, 256>>>(h2, agg);
    gemm_mma<128, true ><<<GB, 256, SM128>>>(agg, whi + 4*32768, wlo + 4*32768, bA[2], hid);
    gemm_mma<64,  false><<<GB, 256, SM64 >>>(hid, whi + 5*32768, wlo + 5*32768, bB[2], h1);
    stats_kernel<64><<<SG, 256>>>(h1);
    bn_finalize_kernel<<<1, 64>>>(gam[2], bet[2], 64);

    // ---- global mean pool (BN+ReLU fused) ----
    pool_sum_kernel<<<(NN * 16 + 255)/256, 256>>>(h1, batch);
    pool_cnt_kernel<<<296, 256>>>(batch);
    pool_fin_kernel<<<(NGR * DO_ + 255)/256, 256>>>((float*)d_out);
}

// round 9
// speedup vs baseline: 1.7883x; 1.1932x over previous
#include <cuda_runtime.h>
#include <cuda_bf16.h>
#include <cstdint>

#define NN   100000
#define NE   1600000
#define NGR  128
#define D_   128
#define DO_  64
#define BN_EPS 1e-5f
#define SCAN_ELEMS 2048
#define NBLK ((NN + SCAN_ELEMS - 1) / SCAN_ELEMS)   // 49

typedef unsigned long long ull;

// ---------------- scratch ----------------
__device__ __align__(16) float g_agg[(size_t)NN * D_];
__device__ __align__(16) float g_h1 [(size_t)NN * D_];
__device__ __align__(16) float g_h2 [(size_t)NN * D_];
__device__ __align__(16) float g_bnstats[2 * D_];   // zero at module init; finalize re-zeroes
__device__ __align__(16) float g_scale[D_];
__device__ __align__(16) float g_shift[D_];
__device__ __align__(16) float g_pool[NGR * DO_];
__device__ __align__(16) int   g_cnt[NGR];
// CSR scratch
__device__ __align__(16) int g_deg[NN];             // zero at init; scan3 re-zeroes
__device__ __align__(16) int g_off[NN + 1];
__device__ __align__(16) int g_cur[NN];
__device__ __align__(16) int g_csr[NE];
__device__ int g_bsum[64];
__device__ int g_bscan[64];
// pre-split, pre-swizzled W images: [k][n] row-major bf16, 16B-chunk XOR swizzle
__device__ __align__(16) unsigned char g_whi[6 * 32768];
__device__ __align__(16) unsigned char g_wlo[6 * 32768];

// ---------------- asm helpers ----------------
__device__ __forceinline__ uint32_t smem_u32(const void* p) {
    uint32_t a;
    asm("{ .reg .u64 t; cvta.to.shared.u64 t, %1; cvt.u32.u64 %0, t; }" : "=r"(a) : "l"(p));
    return a;
}
__device__ __forceinline__ void ldsm_x4(uint32_t& r0, uint32_t& r1, uint32_t& r2, uint32_t& r3,
                                        uint32_t addr) {
    asm volatile("ldmatrix.sync.aligned.m8n8.x4.shared.b16 {%0,%1,%2,%3}, [%4];"
                 : "=r"(r0), "=r"(r1), "=r"(r2), "=r"(r3) : "r"(addr));
}
__device__ __forceinline__ void ldsm_x4t(uint32_t& r0, uint32_t& r1, uint32_t& r2, uint32_t& r3,
                                         uint32_t addr) {
    asm volatile("ldmatrix.sync.aligned.m8n8.x4.trans.shared.b16 {%0,%1,%2,%3}, [%4];"
                 : "=r"(r0), "=r"(r1), "=r"(r2), "=r"(r3) : "r"(addr));
}
__device__ __forceinline__ void mma16816(float* c, uint32_t a0, uint32_t a1, uint32_t a2,
                                         uint32_t a3, uint32_t b0, uint32_t b1) {
    asm volatile("mma.sync.aligned.m16n8k16.row.col.f32.bf16.bf16.f32 "
                 "{%0,%1,%2,%3}, {%4,%5,%6,%7}, {%8,%9}, {%0,%1,%2,%3};"
                 : "+f"(c[0]), "+f"(c[1]), "+f"(c[2]), "+f"(c[3])
                 : "r"(a0), "r"(a1), "r"(a2), "r"(a3), "r"(b0), "r"(b1));
}

// ---------------- CSR build ----------------
__global__ void hist_kernel(const int* __restrict__ dst) {
    int i = blockIdx.x * blockDim.x + threadIdx.x;
    if (i < NE) atomicAdd(&g_deg[__ldg(dst + i)], 1);
}
__global__ void scan_pass1() {
    __shared__ int ssum[8];
    int b = blockIdx.x, tid = threadIdx.x;
    int base = b * SCAN_ELEMS + tid * 8;
    int s = 0;
    #pragma unroll
    for (int j = 0; j < 8; j++) { int idx = base + j; s += (idx < NN) ? g_deg[idx] : 0; }
    #pragma unroll
    for (int o = 16; o; o >>= 1) s += __shfl_down_sync(0xffffffffu, s, o);
    if ((tid & 31) == 0) ssum[tid >> 5] = s;
    __syncthreads();
    if (tid == 0) {
        int t = 0;
        #pragma unroll
        for (int i = 0; i < 8; i++) t += ssum[i];
        g_bsum[b] = t;
    }
}
__global__ void scan_pass2() {
    int tid = threadIdx.x;
    int v = (tid < NBLK) ? g_bsum[tid] : 0;
    int incl = v, lane = tid & 31;
    #pragma unroll
    for (int o = 1; o < 32; o <<= 1) {
        int y = __shfl_up_sync(0xffffffffu, incl, o);
        if (lane >= o) incl += y;
    }
    __shared__ int w0;
    if (tid == 31) w0 = incl;
    __syncthreads();
    if (tid >= 32) incl += w0;
    if (tid < 64) g_bscan[tid] = incl - v;
    if (tid == 0) g_off[NN] = NE;
}
__global__ void scan_pass3() {
    int b = blockIdx.x, tid = threadIdx.x;
    int base = b * SCAN_ELEMS + tid * 8;
    int vals[8], t = 0;
    #pragma unroll
    for (int j = 0; j < 8; j++) { vals[j] = (base + j < NN) ? g_deg[base + j] : 0; t += vals[j]; }
    int lane = tid & 31, wid = tid >> 5, incl = t;
    #pragma unroll
    for (int o = 1; o < 32; o <<= 1) {
        int y = __shfl_up_sync(0xffffffffu, incl, o);
        if (lane >= o) incl += y;
    }
    __shared__ int wsum[8], woff[8];
    if (lane == 31) wsum[wid] = incl;
    __syncthreads();
    if (tid == 0) { int a = 0; for (int i = 0; i < 8; i++) { woff[i] = a; a += wsum[i]; } }
    __syncthreads();
    int run = g_bscan[b] + woff[wid] + (incl - t);
    #pragma unroll
    for (int j = 0; j < 8; j++) {
        int idx = base + j;
        if (idx < NN) {
            g_off[idx] = run; g_cur[idx] = run; run += vals[j];
            g_deg[idx] = 0;   // reset for next replay
        }
    }
}
__global__ void fill_kernel(const int* __restrict__ src, const int* __restrict__ dst) {
    int i = blockIdx.x * blockDim.x + threadIdx.x;
    if (i < NE) {
        int d = __ldg(dst + i);
        int p = atomicAdd(&g_cur[d], 1);
        g_csr[p] = __ldg(src + i);
    }
}

// ---------------- W split + swizzle preconvert (+ pool/cnt zeroing) ----------------
__global__ void wconv_kernel(const float* w0, const float* w1, const float* w2,
                             const float* w3, const float* w4, const float* w5)
{
    int i = blockIdx.x * blockDim.x + threadIdx.x;
    if (i < NGR * DO_) g_pool[i] = 0.f;
    if (i < NGR) g_cnt[i] = 0;
    if (i >= 5 * 16384 + 8192) return;
    int seg = i >> 14;
    int t = i & 16383;
    int nout = (seg == 5) ? 64 : 128;
    const float* W = (seg == 0) ? w0 : (seg == 1) ? w1 : (seg == 2) ? w2
                   : (seg == 3) ? w3 : (seg == 4) ? w4 : w5;
    int k = t / nout, n = t % nout;
    float w = __ldg(W + k * nout + n);
    __nv_bfloat16 hi = __float2bfloat16(w);
    __nv_bfloat16 lo = __float2bfloat16(w - __bfloat162float(hi));
    int pos = k * nout + ((((n >> 3) ^ (k & 7)) << 3) | (n & 7));
    ((__nv_bfloat16*)(g_whi + seg * 32768))[pos] = hi;
    ((__nv_bfloat16*)(g_wlo + seg * 32768))[pos] = lo;
}

// ---------------- gather (exact R4: scalar index loads, 4-edge unroll) ----------------
__device__ __forceinline__ float4 bn_ap(float4 v, float4 sc, float4 sh, bool bn) {
    if (bn) {
        v.x = fmaxf(fmaf(v.x, sc.x, sh.x), 0.f);
        v.y = fmaxf(fmaf(v.y, sc.y, sh.y), 0.f);
        v.z = fmaxf(fmaf(v.z, sc.z, sh.z), 0.f);
        v.w = fmaxf(fmaf(v.w, sc.w, sh.w), 0.f);
    }
    return v;
}
__device__ __forceinline__ void f4acc(float4& a, float4 b) {
    a.x += b.x; a.y += b.y; a.z += b.z; a.w += b.w;
}

template<bool BN>
__global__ void gather_kernel(const float* __restrict__ h, float* __restrict__ out)
{
    int n = blockIdx.x * 8 + (threadIdx.x >> 5);
    if (n >= NN) return;
    int lane = threadIdx.x & 31;
    const float4* __restrict__ h4 = (const float4*)h;

    float4 sc = make_float4(0,0,0,0), sh = make_float4(0,0,0,0);
    if (BN) {
        sc = *(const float4*)(g_scale + lane * 4);
        sh = *(const float4*)(g_shift + lane * 4);
    }
    float4 a0 = bn_ap(__ldg(&h4[(size_t)n * 32 + lane]), sc, sh, BN);
    float4 a1 = make_float4(0,0,0,0), a2 = make_float4(0,0,0,0), a3 = make_float4(0,0,0,0);

    int j = g_off[n], e1 = g_off[n + 1];
    for (; j + 4 <= e1; j += 4) {
        int i0 = __ldg(&g_csr[j]);
        int i1 = __ldg(&g_csr[j + 1]);
        int i2 = __ldg(&g_csr[j + 2]);
        int i3 = __ldg(&g_csr[j + 3]);
        float4 w0 = __ldg(&h4[(size_t)i0 * 32 + lane]);
        float4 w1 = __ldg(&h4[(size_t)i1 * 32 + lane]);
        float4 w2 = __ldg(&h4[(size_t)i2 * 32 + lane]);
        float4 w3 = __ldg(&h4[(size_t)i3 * 32 + lane]);
        f4acc(a0, bn_ap(w0, sc, sh, BN));
        f4acc(a1, bn_ap(w1, sc, sh, BN));
        f4acc(a2, bn_ap(w2, sc, sh, BN));
        f4acc(a3, bn_ap(w3, sc, sh, BN));
    }
    for (; j < e1; j++) {
        int s = __ldg(&g_csr[j]);
        f4acc(a0, bn_ap(__ldg(&h4[(size_t)s * 32 + lane]), sc, sh, BN));
    }
    f4acc(a0, a1); f4acc(a2, a3); f4acc(a0, a2);
    ((float4*)out)[(size_t)n * 32 + lane] = a0;
}

// ---------------- fused 2-GEMM MLP (mma.sync, split-bf16 3-term, NO stats atomics) ----
// out[N,NOUT] = ReLU(A[N,128] @ W1 + b1) @ W2 + b2 ; 256 thr, 128-row tile.
template<int NT>
__device__ __forceinline__ void mma_loop(uint32_t sb, uint32_t aHi, uint32_t aLo,
                                         uint32_t bHi, uint32_t bLo,
                                         int wid, int lane, float acc[][4])
{
    const int la = lane & 15;
    const int lb = lane >> 4;
    const int l7 = lane & 7;
    const int BR = NT * 16;
    const uint32_t aRow = (uint32_t)((wid * 16 + la) * 256);
    const uint32_t bRow = (uint32_t)(la * BR);
    #pragma unroll 2
    for (int k0 = 0; k0 < 128; k0 += 16) {
        uint32_t kc = (uint32_t)((k0 >> 3) + lb);
        uint32_t aoff = aRow + ((kc ^ (uint32_t)l7) << 4);
        uint32_t ah0, ah1, ah2, ah3, al0, al1, al2, al3;
        ldsm_x4(ah0, ah1, ah2, ah3, sb + aHi + aoff);
        ldsm_x4(al0, al1, al2, al3, sb + aLo + aoff);
        uint32_t bbase = (uint32_t)(k0 * BR) + bRow;
        #pragma unroll
        for (int nt = 0; nt < NT; nt += 2) {
            uint32_t boff = bbase + ((((uint32_t)(nt + lb)) ^ (uint32_t)l7) << 4);
            uint32_t bh0, bh1, bh2, bh3, bl0, bl1, bl2, bl3;
            ldsm_x4t(bh0, bh1, bh2, bh3, sb + bHi + boff);
            ldsm_x4t(bl0, bl1, bl2, bl3, sb + bLo + boff);
            mma16816(acc[nt],     ah0, ah1, ah2, ah3, bh0, bh1);
            mma16816(acc[nt + 1], ah0, ah1, ah2, ah3, bh2, bh3);
            mma16816(acc[nt],     ah0, ah1, ah2, ah3, bl0, bl1);
            mma16816(acc[nt + 1], ah0, ah1, ah2, ah3, bl2, bl3);
            mma16816(acc[nt],     al0, al1, al2, al3, bh0, bh1);
            mma16816(acc[nt + 1], al0, al1, al2, al3, bh2, bh3);
        }
    }
}

template<int NOUT>
__global__ __launch_bounds__(256, 1)
void mlp_mma(const float* __restrict__ A,
             const unsigned char* __restrict__ w1h, const unsigned char* __restrict__ w1l,
             const float* __restrict__ b1,
             const unsigned char* __restrict__ w2h, const unsigned char* __restrict__ w2l,
             const float* __restrict__ b2, float* __restrict__ out)
{
    constexpr int NT2  = NOUT / 8;
    constexpr int AHI  = 0;
    constexpr int ALO  = 32768;
    constexpr int B1HI = 65536;
    constexpr int B1LO = 98304;
    constexpr int B2HI = 131072;
    constexpr int B2LO = 131072 + NOUT * 256;

    extern __shared__ __align__(16) char smem[];
    const uint32_t sb = smem_u32(smem);
    const int tid  = threadIdx.x;
    const int wid  = tid >> 5;
    const int lane = tid & 31;
    const int row0 = blockIdx.x * 128;

    // B tiles: straight copies of pre-swizzled images
    {
        const float4* s1 = (const float4*)w1h;
        const float4* s2 = (const float4*)w1l;
        float4* d1 = (float4*)(smem + B1HI);
        float4* d2 = (float4*)(smem + B1LO);
        #pragma unroll
        for (int i = tid; i < 2048; i += 256) { d1[i] = s1[i]; d2[i] = s2[i]; }
        const float4* s3 = (const float4*)w2h;
        const float4* s4 = (const float4*)w2l;
        float4* d3 = (float4*)(smem + B2HI);
        float4* d4 = (float4*)(smem + B2LO);
        #pragma unroll
        for (int i = tid; i < NOUT * 16; i += 256) { d3[i] = s3[i]; d4[i] = s4[i]; }
    }
    // A tile: fp32 -> bf16 hi/lo, swizzled 16B chunks (chunk c at c ^ (r&7))
    for (int i = tid; i < 2048; i += 256) {
        int r = i >> 4, c = i & 15;
        int gr = row0 + r;
        float4 v0 = make_float4(0,0,0,0), v1 = make_float4(0,0,0,0);
        if (gr < NN) {
            const float4* ap = (const float4*)(A + (size_t)gr * 128 + c * 8);
            v0 = __ldg(ap); v1 = __ldg(ap + 1);
        }
        float vv[8] = {v0.x, v0.y, v0.z, v0.w, v1.x, v1.y, v1.z, v1.w};
        uint4 hq, lq;
        uint32_t* hp = (uint32_t*)&hq;
        uint32_t* lp = (uint32_t*)&lq;
        #pragma unroll
        for (int p = 0; p < 4; p++) {
            __nv_bfloat162 h2, l2;
            h2.x = __float2bfloat16(vv[2*p]);
            h2.y = __float2bfloat16(vv[2*p+1]);
            l2.x = __float2bfloat16(vv[2*p]   - __bfloat162float(h2.x));
            l2.y = __float2bfloat16(vv[2*p+1] - __bfloat162float(h2.y));
            hp[p] = *(uint32_t*)&h2;
            lp[p] = *(uint32_t*)&l2;
        }
        uint32_t off = (uint32_t)(r * 256 + ((c ^ (r & 7)) << 4));
        *(uint4*)(smem + AHI + off) = hq;
        *(uint4*)(smem + ALO + off) = lq;
    }
    __syncthreads();

    // ---- stage 1: hid = ReLU(A @ W1 + b1) ----
    float acc[16][4];
    #pragma unroll
    for (int t = 0; t < 16; t++)
        #pragma unroll
        for (int e = 0; e < 4; e++) acc[t][e] = 0.f;
    mma_loop<16>(sb, AHI, ALO, B1HI, B1LO, wid, lane, acc);
    __syncthreads();   // all warps done reading A tile

    // epilogue 1: bias+ReLU, split to bf16, write back into A buffers (swizzled, conflict-free)
    {
        int rr1 = wid * 16 + (lane >> 2);
        int rr2 = rr1 + 8;
        uint32_t cb1 = (uint32_t)(rr1 * 256);
        uint32_t cb2 = (uint32_t)(rr2 * 256);
        int sw1 = (rr1 & 7), sw2 = (rr2 & 7);
        int cpos = (lane & 3) * 4;
        #pragma unroll
        for (int nt = 0; nt < 16; nt++) {
            int col = nt * 8 + (lane & 3) * 2;
            float2 bb = __ldg((const float2*)(b1 + col));
            float v0 = fmaxf(acc[nt][0] + bb.x, 0.f);
            float v1 = fmaxf(acc[nt][1] + bb.y, 0.f);
            float v2 = fmaxf(acc[nt][2] + bb.x, 0.f);
            float v3 = fmaxf(acc[nt][3] + bb.y, 0.f);
            __nv_bfloat162 h2, l2;
            h2.x = __float2bfloat16(v0);
            h2.y = __float2bfloat16(v1);
            l2.x = __float2bfloat16(v0 - __bfloat162float(h2.x));
            l2.y = __float2bfloat16(v1 - __bfloat162float(h2.y));
            uint32_t o1 = cb1 + ((uint32_t)(nt ^ sw1) << 4) + cpos;
            *(uint32_t*)(smem + AHI + o1) = *(uint32_t*)&h2;
            *(uint32_t*)(smem + ALO + o1) = *(uint32_t*)&l2;
            h2.x = __float2bfloat16(v2);
            h2.y = __float2bfloat16(v3);
            l2.x = __float2bfloat16(v2 - __bfloat162float(h2.x));
            l2.y = __float2bfloat16(v3 - __bfloat162float(h2.y));
            uint32_t o2 = cb2 + ((uint32_t)(nt ^ sw2) << 4) + cpos;
            *(uint32_t*)(smem + AHI + o2) = *(uint32_t*)&h2;
            *(uint32_t*)(smem + ALO + o2) = *(uint32_t*)&l2;
        }
    }
    __syncthreads();

    // ---- stage 2: out = hid @ W2 + b2 ----
    float acc2[NT2][4];
    #pragma unroll
    for (int t = 0; t < NT2; t++)
        #pragma unroll
        for (int e = 0; e < 4; e++) acc2[t][e] = 0.f;
    mma_loop<NT2>(sb, AHI, ALO, B2HI, B2LO, wid, lane, acc2);

    int r1 = row0 + wid * 16 + (lane >> 2);
    int r2 = r1 + 8;
    #pragma unroll
    for (int nt = 0; nt < NT2; nt++) {
        int col = nt * 8 + (lane & 3) * 2;
        float2 bb = __ldg((const float2*)(b2 + col));
        float v0 = acc2[nt][0] + bb.x;
        float v1 = acc2[nt][1] + bb.y;
        float v2 = acc2[nt][2] + bb.x;
        float v3 = acc2[nt][3] + bb.y;
        if (r1 < NN) *(float2*)(out + (size_t)r1 * NOUT + col) = make_float2(v0, v1);
        if (r2 < NN) *(float2*)(out + (size_t)r2 * NOUT + col) = make_float2(v2, v3);
    }
}

// ---------------- BN column stats (separate, coalesced — R4-proven) ----------------
template<int NOUT>
__global__ void stats_kernel(const float* __restrict__ h)
{
    constexpr int QC = NOUT / 4;
    constexpr int STEP = 256 / QC;
    __shared__ float ss[NOUT], sq[NOUT];
    int tid = threadIdx.x;
    if (tid < NOUT) { ss[tid] = 0.f; sq[tid] = 0.f; }
    __syncthreads();
    int qc = tid % QC, rg = tid / QC;
    int rend = min(blockIdx.x * 512 + 512, NN);
    float4 s4 = make_float4(0,0,0,0), q4 = make_float4(0,0,0,0);
    for (int r = blockIdx.x * 512 + rg; r < rend; r += STEP) {
        float4 v = __ldg((const float4*)(h + (size_t)r * NOUT) + qc);
        s4.x += v.x; s4.y += v.y; s4.z += v.z; s4.w += v.w;
        q4.x += v.x*v.x; q4.y += v.y*v.y; q4.z += v.z*v.z; q4.w += v.w*v.w;
    }
    int c = qc * 4;
    atomicAdd(&ss[c+0], s4.x); atomicAdd(&ss[c+1], s4.y);
    atomicAdd(&ss[c+2], s4.z); atomicAdd(&ss[c+3], s4.w);
    atomicAdd(&sq[c+0], q4.x); atomicAdd(&sq[c+1], q4.y);
    atomicAdd(&sq[c+2], q4.z); atomicAdd(&sq[c+3], q4.w);
    __syncthreads();
    if (tid < NOUT) {
        atomicAdd(&g_bnstats[tid], ss[tid]);
        atomicAdd(&g_bnstats[NOUT + tid], sq[tid]);
    }
}

// ---------------- BN finalize (resets stats after read) ----------------
__global__ void bn_finalize_kernel(const float* __restrict__ gamma,
                                   const float* __restrict__ beta, int nout)
{
    int c = threadIdx.x;
    if (c < nout) {
        const float invN = 1.0f / (float)NN;
        float sv = g_bnstats[c];
        float qv = g_bnstats[nout + c];
        float mu  = sv * invN;
        float var = qv * invN - mu * mu;
        float s   = gamma[c] * rsqrtf(var + BN_EPS);
        g_scale[c] = s;
        g_shift[c] = beta[c] - mu * s;
        g_bnstats[c] = 0.f;
        g_bnstats[nout + c] = 0.f;
    }
}

// ---------------- pooling (BN+ReLU fused) ----------------
__global__ void pool_sum_kernel(const float* __restrict__ pre, const int* __restrict__ batch)
{
    int t = blockIdx.x * blockDim.x + threadIdx.x;
    if (t >= NN * 16) return;
    int n = t >> 4, q = t & 15;
    int c = q << 2;
    int b = __ldg(batch + n);
    float4 v  = *(const float4*)(pre + (size_t)n * DO_ + c);
    float4 sc = *(const float4*)(g_scale + c);
    float4 sh = *(const float4*)(g_shift + c);
    v.x = fmaxf(fmaf(v.x, sc.x, sh.x), 0.f);
    v.y = fmaxf(fmaf(v.y, sc.y, sh.y), 0.f);
    v.z = fmaxf(fmaf(v.z, sc.z, sh.z), 0.f);
    v.w = fmaxf(fmaf(v.w, sc.w, sh.w), 0.f);
    float* p = g_pool + b * DO_ + c;
    asm volatile("red.global.add.v4.f32 [%0], {%1, %2, %3, %4};"
                 :: "l"(p), "f"(v.x), "f"(v.y), "f"(v.z), "f"(v.w) : "memory");
}

__global__ void pool_cnt_kernel(const int* __restrict__ batch)
{
    __shared__ int sc[NGR];
    for (int i = threadIdx.x; i < NGR; i += blockDim.x) sc[i] = 0;
    __syncthreads();
    for (int i = blockIdx.x * blockDim.x + threadIdx.x; i < NN; i += gridDim.x * blockDim.x)
        atomicAdd(&sc[__ldg(batch + i)], 1);
    __syncthreads();
    for (int i = threadIdx.x; i < NGR; i += blockDim.x)
        if (sc[i]) atomicAdd(&g_cnt[i], sc[i]);
}

__global__ void pool_fin_kernel(float* __restrict__ out)
{
    int i = blockIdx.x * blockDim.x + threadIdx.x;
    if (i < NGR * DO_) {
        int g = i >> 6;
        float c = (float)(g_cnt[g] > 0 ? g_cnt[g] : 1);
        out[i] = g_pool[i] / c;
    }
}

// ---------------- launcher ----------------
extern "C" void kernel_launch(void* const* d_in, const int* in_sizes, int n_in,
                              void* d_out, int out_size)
{
    const float* x     = (const float*)d_in[0];
    const int*   ei    = (const int*)d_in[1];
    const int*   batch = (const int*)d_in[2];
    const float *wA[3], *bA[3], *wB[3], *bB[3], *gam[3], *bet[3];
    for (int l = 0; l < 3; l++) {
        wA[l]  = (const float*)d_in[3 + 6*l + 0];
        bA[l]  = (const float*)d_in[3 + 6*l + 1];
        wB[l]  = (const float*)d_in[3 + 6*l + 2];
        bB[l]  = (const float*)d_in[3 + 6*l + 3];
        gam[l] = (const float*)d_in[3 + 6*l + 4];
        bet[l] = (const float*)d_in[3 + 6*l + 5];
    }
    const int* src = ei;
    const int* dst = ei + NE;

    float *agg, *h1, *h2;
    unsigned char *whi, *wlo;
    cudaGetSymbolAddress((void**)&agg,  g_agg);
    cudaGetSymbolAddress((void**)&h1,   g_h1);
    cudaGetSymbolAddress((void**)&h2,   g_h2);
    cudaGetSymbolAddress((void**)&whi,  g_whi);
    cudaGetSymbolAddress((void**)&wlo,  g_wlo);

    constexpr int SMF128 = 65536 + 65536 + 65536;  // 196608
    constexpr int SMF64  = 65536 + 65536 + 32768;  // 163840
    cudaFuncSetAttribute(mlp_mma<128>, cudaFuncAttributeMaxDynamicSharedMemorySize, SMF128);
    cudaFuncSetAttribute(mlp_mma<64>,  cudaFuncAttributeMaxDynamicSharedMemorySize, SMF64);

    const int GB = (NN + 127) / 128;   // 782
    const int EG = (NE + 255) / 256;
    const int GG = (NN + 7) / 8;
    const int SG = (NN + 511) / 512;

    // ---- CSR build ----
    hist_kernel<<<EG, 256>>>(dst);
    scan_pass1<<<NBLK, 256>>>();
    scan_pass2<<<1, 64>>>();
    scan_pass3<<<NBLK, 256>>>();
    fill_kernel<<<EG, 256>>>(src, dst);

    // ---- W preconvert (+ pool/cnt zeroing) ----
    wconv_kernel<<<(5*16384 + 8192 + 255)/256, 256>>>(wA[0], wB[0], wA[1], wB[1], wA[2], wB[2]);

    // ---- layer 0 ----
    gather_kernel<false><<<GG, 256>>>(x, agg);
    mlp_mma<128><<<GB, 256, SMF128>>>(agg, whi + 0*32768, wlo + 0*32768, bA[0],
                                      whi + 1*32768, wlo + 1*32768, bB[0], h1);
    stats_kernel<128><<<SG, 256>>>(h1);
    bn_finalize_kernel<<<1, 128>>>(gam[0], bet[0], 128);

    // ---- layer 1 ----
    gather_kernel<true><<<GG, 256>>>(h1, agg);
    mlp_mma<128><<<GB, 256, SMF128>>>(agg, whi + 2*32768, wlo + 2*32768, bA[1],
                                      whi + 3*32768, wlo + 3*32768, bB[1], h2);
    stats_kernel<128><<<SG, 256>>>(h2);
    bn_finalize_kernel<<<1, 128>>>(gam[1], bet[1], 128);

    // ---- layer 2 ----
    gather_kernel<true><<<GG, 256>>>(h2, agg);
    mlp_mma<64><<<GB, 256, SMF64>>>(agg, whi + 4*32768, wlo + 4*32768, bA[2],
                                    whi + 5*32768, wlo + 5*32768, bB[2], h1);
    stats_kernel<64><<<SG, 256>>>(h1);
    bn_finalize_kernel<<<1, 64>>>(gam[2], bet[2], 64);

    // ---- global mean pool (BN+ReLU fused) ----
    pool_sum_kernel<<<(NN * 16 + 255)/256, 256>>>(h1, batch);
    pool_cnt_kernel<<<296, 256>>>(batch);
    pool_fin_kernel<<<(NGR * DO_ + 255)/256, 256>>>((float*)d_out);
}